// round 4
// baseline (speedup 1.0000x reference)
#include <cuda_runtime.h>
#include <cstdint>
#include <cstddef>

#define S_LEN 512
#define BATCH 64
#define HID   1024
#define NG    4096            // 4*HID
#define MTOT  (S_LEN*BATCH)   // 32768
#define GRID  128             // persistent CTAs (HID/8)
#define WSTR  1028            // Ws row stride (floats): %32==4 -> conflict-free b-frags
#define ASTR  68              // As row stride (floats): %32==4 -> conflict-free a-frags
#define NSTG  4               // cp.async stages
#define KCH   64              // k per chunk
#define NCHK  (HID/KCH)       // 16 chunks per step

// ---- scratch (device globals; no runtime allocation) ----
__device__ float g_gx[(size_t)MTOT * NG];   // precomputed x@W_ih^T + b
__device__ float g_h[2][BATCH * HID];       // double-buffered hidden state (tf32-rounded)
__device__ float g_c[BATCH * HID];          // cell state (fp32)
__device__ float g_b[NG];                   // b_ih + b_hh
__device__ float g_wsum[(size_t)NG * HID];  // W_ih + W_hh (AR steps)
__device__ unsigned g_bar;                  // grid barrier counter

// ---- tf32 helpers ----
__device__ __forceinline__ float tfr(float f) {
    unsigned u;
    asm("cvt.rna.tf32.f32 %0, %1;" : "=r"(u) : "f"(f));
    return __uint_as_float(u);
}

__device__ __forceinline__ void mma_tf32(float c[4], const unsigned a[4], const unsigned b[2]) {
    asm volatile(
        "mma.sync.aligned.m16n8k8.row.col.f32.tf32.tf32.f32 "
        "{%0,%1,%2,%3}, {%4,%5,%6,%7}, {%8,%9}, {%0,%1,%2,%3};\n"
        : "+f"(c[0]), "+f"(c[1]), "+f"(c[2]), "+f"(c[3])
        : "r"(a[0]), "r"(a[1]), "r"(a[2]), "r"(a[3]), "r"(b[0]), "r"(b[1]));
}

#define CP_ASYNC16(dst_u32, src) \
    asm volatile("cp.async.cg.shared.global [%0], [%1], 16;\n" :: "r"(dst_u32), "l"(src))
#define CP_COMMIT() asm volatile("cp.async.commit_group;\n" ::: "memory")
#define CP_WAIT2()  asm volatile("cp.async.wait_group 2;\n" ::: "memory")

// ============================================================================
// prep: b = b_ih + b_hh ; Wsum = W_ih + W_hh ; h0 (tf32-rounded), c0 ; barrier=0
// ============================================================================
__global__ void prep_kernel(const float* __restrict__ W_ih, const float* __restrict__ W_hh,
                            const float* __restrict__ b_ih, const float* __restrict__ b_hh,
                            const float* __restrict__ hx0,  const float* __restrict__ cx0) {
    int idx = blockIdx.x * blockDim.x + threadIdx.x;
    if (idx == 0) g_bar = 0;
    if (idx < NG * HID) g_wsum[idx] = W_ih[idx] + W_hh[idx];
    if (idx < NG)       g_b[idx]    = b_ih[idx] + b_hh[idx];
    if (idx < BATCH * HID) {
        g_h[0][idx] = tfr(hx0[idx]);   // matmul input; tf32 rounding point unchanged
        g_c[idx]    = cx0[idx];
    }
}

// ============================================================================
// gemmA: g_gx[M=32768, NG=4096] = X[M,1024] @ W_ih^T + b   (tf32 MMA)
// (unchanged from R3 — known working; next optimization target)
// ============================================================================
__global__ __launch_bounds__(256) void gemmA_kernel(const float* __restrict__ X,
                                                    const float* __restrict__ W) {
    __shared__ float As[128][36];
    __shared__ float Bs[64][36];

    const int tid  = threadIdx.x;
    const int wid  = tid >> 5, lane = tid & 31;
    const int wm   = wid >> 1;
    const int wn   = wid & 1;
    const int m0   = blockIdx.y * 128;
    const int n0   = blockIdx.x * 64;

    const float* Ag = X + (size_t)m0 * HID;
    const float* Bg = W + (size_t)n0 * HID;

    float c[2][4][4];
    #pragma unroll
    for (int mt = 0; mt < 2; mt++)
        #pragma unroll
        for (int nt = 0; nt < 4; nt++)
            #pragma unroll
            for (int r = 0; r < 4; r++) c[mt][nt][r] = 0.f;

    float4 ra[4], rb[2];
    auto loadG = [&](int kc) {
        const int k0 = kc * 32;
        #pragma unroll
        for (int i = 0; i < 4; i++) {
            int l = tid + i * 256;
            int r = l >> 3, f = l & 7;
            ra[i] = *reinterpret_cast<const float4*>(Ag + (size_t)r * HID + k0 + f * 4);
        }
        #pragma unroll
        for (int i = 0; i < 2; i++) {
            int l = tid + i * 256;
            int r = l >> 3, f = l & 7;
            rb[i] = *reinterpret_cast<const float4*>(Bg + (size_t)r * HID + k0 + f * 4);
        }
    };

    loadG(0);
    for (int kc = 0; kc < 32; kc++) {
        #pragma unroll
        for (int i = 0; i < 4; i++) {
            int l = tid + i * 256;
            int r = l >> 3, f = l & 7;
            float4 v = ra[i];
            v.x = tfr(v.x); v.y = tfr(v.y); v.z = tfr(v.z); v.w = tfr(v.w);
            *reinterpret_cast<float4*>(&As[r][f * 4]) = v;
        }
        #pragma unroll
        for (int i = 0; i < 2; i++) {
            int l = tid + i * 256;
            int r = l >> 3, f = l & 7;
            float4 v = rb[i];
            v.x = tfr(v.x); v.y = tfr(v.y); v.z = tfr(v.z); v.w = tfr(v.w);
            *reinterpret_cast<float4*>(&Bs[r][f * 4]) = v;
        }
        __syncthreads();
        if (kc + 1 < 32) loadG(kc + 1);

        #pragma unroll
        for (int kk = 0; kk < 4; kk++) {
            const int k8 = kk * 8;
            unsigned a[2][4], b[4][2];
            #pragma unroll
            for (int mt = 0; mt < 2; mt++) {
                int r0 = wm * 32 + mt * 16 + (lane >> 2);
                a[mt][0] = __float_as_uint(As[r0][k8 + (lane & 3)]);
                a[mt][1] = __float_as_uint(As[r0 + 8][k8 + (lane & 3)]);
                a[mt][2] = __float_as_uint(As[r0][k8 + (lane & 3) + 4]);
                a[mt][3] = __float_as_uint(As[r0 + 8][k8 + (lane & 3) + 4]);
            }
            #pragma unroll
            for (int nt = 0; nt < 4; nt++) {
                int rn = wn * 32 + nt * 8 + (lane >> 2);
                b[nt][0] = __float_as_uint(Bs[rn][k8 + (lane & 3)]);
                b[nt][1] = __float_as_uint(Bs[rn][k8 + (lane & 3) + 4]);
            }
            #pragma unroll
            for (int mt = 0; mt < 2; mt++)
                #pragma unroll
                for (int nt = 0; nt < 4; nt++)
                    mma_tf32(c[mt][nt], a[mt], b[nt]);
        }
        __syncthreads();
    }

    #pragma unroll
    for (int mt = 0; mt < 2; mt++) {
        #pragma unroll
        for (int nt = 0; nt < 4; nt++) {
            int row = m0 + wm * 32 + mt * 16 + (lane >> 2);
            int col = n0 + wn * 32 + nt * 8 + 2 * (lane & 3);
            float b0 = g_b[col], b1 = g_b[col + 1];
            g_gx[(size_t)row * NG + col]           = c[mt][nt][0] + b0;
            g_gx[(size_t)row * NG + col + 1]       = c[mt][nt][1] + b1;
            g_gx[(size_t)(row + 8) * NG + col]     = c[mt][nt][2] + b0;
            g_gx[(size_t)(row + 8) * NG + col + 1] = c[mt][nt][3] + b1;
        }
    }
}

// ============================================================================
// persist: all 512 recurrent steps; W_hh slice resident in SMEM;
// h streamed via 4-stage cp.async.cg pipeline (1 sync per 64-col chunk).
// SMEM: Ws[32][WSTR] (128.5KB) | As stages 4x[64][ASTR] (68KB). sg aliases stage0.
// ============================================================================
__global__ __launch_bounds__(256) void persist_kernel(const float* __restrict__ Whh) {
    extern __shared__ float sm[];
    float* Ws  = sm;                           // [32][WSTR]
    float* AsB = sm + 32 * WSTR;               // NSTG x [64][ASTR]
    float* sg  = AsB;                          // epilogue scratch (aliases stage 0)

    const int tid = threadIdx.x, wid = tid >> 5, lane = tid & 31;
    const int wn = wid & 3;                    // gate index
    const int wm = wid >> 2;                   // 0..1
    const int j0 = blockIdx.x * 8;

    // ---- prologue: W_hh slice -> SMEM (tf32) ----
    for (int i = tid; i < 32 * 256; i += 256) {
        int r = i >> 8, f = i & 255;           // r: local row 0..31, f: float4 idx
        int gate = r >> 3, jj = r & 7;
        float4 v = *reinterpret_cast<const float4*>(
            Whh + (size_t)(gate * HID + j0 + jj) * HID + f * 4);
        v.x = tfr(v.x); v.y = tfr(v.y); v.z = tfr(v.z); v.w = tfr(v.w);
        *reinterpret_cast<float4*>(&Ws[r * WSTR + f * 4]) = v;
    }
    __syncthreads();

    const int arow0 = wm * 32 + (lane >> 2);   // a-frag row base
    const int jjc   = 2 * (lane & 3);          // frag col base (within 8)
    const int rn    = wn * 8 + (lane >> 2);    // Ws row for b-frag
    const int c0    = lane & 3;                // frag k base

    // per-thread cp.async geometry: 4 units of 16B; rows (tid>>4)+{0,16,32,48}, f=tid&15
    const int cprow = tid >> 4, cpf = tid & 15;
    unsigned stg_addr[NSTG][4];
    #pragma unroll
    for (int s = 0; s < NSTG; s++)
        #pragma unroll
        for (int i = 0; i < 4; i++)
            stg_addr[s][i] = (unsigned)__cvta_generic_to_shared(
                AsB + s * (64 * ASTR) + (cprow + i * 16) * ASTR + cpf * 4);

    for (int t = 0; t < S_LEN; t++) {
        const float* __restrict__ h_in  = g_h[t & 1];
        float*       __restrict__ h_out = g_h[(t + 1) & 1];
        const float* __restrict__ gx_t  = g_gx + (size_t)t * BATCH * NG;

        auto issueChunk = [&](int kc) {
            const float* base = h_in + kc * KCH + cpf * 4;
            #pragma unroll
            for (int i = 0; i < 4; i++)
                CP_ASYNC16(stg_addr[(kc) & (NSTG - 1)][i],
                           base + (size_t)(cprow + i * 16) * HID);
        };

        // prefetch gx (input projection + bias) — consumed in epilogue
        float gxr[2][4];
        #pragma unroll
        for (int mt = 0; mt < 2; mt++) {
            int row = arow0 + mt * 16;
            int n   = wn * HID + j0 + jjc;
            gxr[mt][0] = gx_t[(size_t)row * NG + n];
            gxr[mt][1] = gx_t[(size_t)row * NG + n + 1];
            gxr[mt][2] = gx_t[(size_t)(row + 8) * NG + n];
            gxr[mt][3] = gx_t[(size_t)(row + 8) * NG + n + 1];
        }

        issueChunk(0); CP_COMMIT();
        issueChunk(1); CP_COMMIT();
        issueChunk(2); CP_COMMIT();

        float c[2][4];
        #pragma unroll
        for (int mt = 0; mt < 2; mt++)
            #pragma unroll
            for (int r = 0; r < 4; r++) c[mt][r] = 0.f;

        for (int kc = 0; kc < NCHK; kc++) {
            CP_WAIT2();
            __syncthreads();
            if (kc + 3 < NCHK) issueChunk(kc + 3);
            CP_COMMIT();                         // empty group when nothing issued

            const float* As = AsB + (kc & (NSTG - 1)) * (64 * ASTR);
            #pragma unroll
            for (int kk = 0; kk < KCH / 8; kk++) {
                const int k8 = kk * 8;
                const int kglob = kc * KCH + k8;
                unsigned a[2][4], b[2];
                #pragma unroll
                for (int mt = 0; mt < 2; mt++) {
                    int r0 = arow0 + mt * 16;
                    a[mt][0] = __float_as_uint(As[r0 * ASTR + k8 + c0]);
                    a[mt][1] = __float_as_uint(As[(r0 + 8) * ASTR + k8 + c0]);
                    a[mt][2] = __float_as_uint(As[r0 * ASTR + k8 + c0 + 4]);
                    a[mt][3] = __float_as_uint(As[(r0 + 8) * ASTR + k8 + c0 + 4]);
                }
                b[0] = __float_as_uint(Ws[rn * WSTR + kglob + c0]);
                b[1] = __float_as_uint(Ws[rn * WSTR + kglob + c0 + 4]);
                #pragma unroll
                for (int mt = 0; mt < 2; mt++)
                    mma_tf32(c[mt], a[mt], b);
            }
        }
        // last chunk read stage 15&3=3; sg (2304 floats) fits inside stage 0 — safe.

        // ---- gate exchange via SMEM ----
        #pragma unroll
        for (int mt = 0; mt < 2; mt++) {
            int row = arow0 + mt * 16;
            sg[(wn * 64 + row) * 9 + jjc]         = c[mt][0] + gxr[mt][0];
            sg[(wn * 64 + row) * 9 + jjc + 1]     = c[mt][1] + gxr[mt][1];
            sg[(wn * 64 + row + 8) * 9 + jjc]     = c[mt][2] + gxr[mt][2];
            sg[(wn * 64 + row + 8) * 9 + jjc + 1] = c[mt][3] + gxr[mt][3];
        }
        __syncthreads();

        // ---- elementwise cell update for 64x8 slice; h stored tf32-rounded ----
        for (int q = tid; q < BATCH * 8; q += 256) {
            int m = q >> 3, jj = q & 7;
            float gi = sg[(0 * 64 + m) * 9 + jj];
            float gf = sg[(1 * 64 + m) * 9 + jj];
            float gg = sg[(2 * 64 + m) * 9 + jj];
            float go = sg[(3 * 64 + m) * 9 + jj];
            int cidx = m * HID + j0 + jj;
            float cold = g_c[cidx];
            float si = 1.f / (1.f + expf(-gi));
            float sf = 1.f / (1.f + expf(-gf));
            float so = 1.f / (1.f + expf(-go));
            float cn = sf * cold + si * tanhf(gg);
            float hn = so * tanhf(cn);
            g_c[cidx]   = cn;
            h_out[cidx] = tfr(hn);
        }

        // ---- grid barrier (monotonic counter; reset by prep each replay) ----
        __syncthreads();
        if (tid == 0) {
            __threadfence();
            atomicAdd(&g_bar, 1u);
            unsigned target = (unsigned)(t + 1) * GRID;
            while (*(volatile unsigned*)&g_bar < target) { }
            __threadfence();   // gpu-scope: CCTL.IVALL flushes this SM's L1
        }
        __syncthreads();
    }
}

// ============================================================================
// ar_step: autoregressive steps (gates = g_b + h @ Wsum^T); writes output
// ============================================================================
__global__ __launch_bounds__(256) void ar_step_kernel(int t, float* __restrict__ out_slot) {
    __shared__ float sm[64 * 36 + 32 * 36];
    float (*As)[36] = reinterpret_cast<float(*)[36]>(sm);
    float (*Bs)[36] = reinterpret_cast<float(*)[36]>(sm + 64 * 36);

    const int tid = threadIdx.x, wid = tid >> 5, lane = tid & 31;
    const int wn = wid & 3;
    const int wm = wid >> 2;
    const int j0 = blockIdx.x * 8;

    const float* __restrict__ h_in  = g_h[t & 1];
    float*       __restrict__ h_out = g_h[(t + 1) & 1];
    const float* __restrict__ W     = g_wsum;

    float c[2][4];
    #pragma unroll
    for (int mt = 0; mt < 2; mt++) {
        int jj = 2 * (lane & 3);
        int n  = wn * HID + j0 + jj;
        float b0 = g_b[n], b1 = g_b[n + 1];
        c[mt][0] = b0; c[mt][1] = b1;
        c[mt][2] = b0; c[mt][3] = b1;
    }

    float4 ra[2], rb;
    auto loadG = [&](int kc) {
        const int k0 = kc * 32;
        #pragma unroll
        for (int i = 0; i < 2; i++) {
            int l = tid + i * 256;
            int r = l >> 3, f = l & 7;
            ra[i] = *reinterpret_cast<const float4*>(h_in + (size_t)r * HID + k0 + f * 4);
        }
        {
            int r = tid >> 3, f = tid & 7;
            int gate = r >> 3, jj2 = r & 7;
            rb = *reinterpret_cast<const float4*>(
                W + (size_t)(gate * HID + j0 + jj2) * HID + k0 + f * 4);
        }
    };

    loadG(0);
    for (int kc = 0; kc < 32; kc++) {
        #pragma unroll
        for (int i = 0; i < 2; i++) {
            int l = tid + i * 256;
            int r = l >> 3, f = l & 7;
            float4 va = ra[i];
            va.x = tfr(va.x); va.y = tfr(va.y); va.z = tfr(va.z); va.w = tfr(va.w);
            *reinterpret_cast<float4*>(&As[r][f * 4]) = va;
        }
        {
            int r = tid >> 3, f = tid & 7;
            float4 vb = rb;
            vb.x = tfr(vb.x); vb.y = tfr(vb.y); vb.z = tfr(vb.z); vb.w = tfr(vb.w);
            *reinterpret_cast<float4*>(&Bs[r][f * 4]) = vb;
        }
        __syncthreads();
        if (kc + 1 < 32) loadG(kc + 1);

        #pragma unroll
        for (int kk = 0; kk < 4; kk++) {
            const int k8 = kk * 8;
            unsigned a[2][4], b[2];
            #pragma unroll
            for (int mt = 0; mt < 2; mt++) {
                int r0 = wm * 32 + mt * 16 + (lane >> 2);
                a[mt][0] = __float_as_uint(As[r0][k8 + (lane & 3)]);
                a[mt][1] = __float_as_uint(As[r0 + 8][k8 + (lane & 3)]);
                a[mt][2] = __float_as_uint(As[r0][k8 + (lane & 3) + 4]);
                a[mt][3] = __float_as_uint(As[r0 + 8][k8 + (lane & 3) + 4]);
            }
            {
                int rb2 = wn * 8 + (lane >> 2);
                b[0] = __float_as_uint(Bs[rb2][k8 + (lane & 3)]);
                b[1] = __float_as_uint(Bs[rb2][k8 + (lane & 3) + 4]);
            }
            #pragma unroll
            for (int mt = 0; mt < 2; mt++)
                mma_tf32(c[mt], a[mt], b);
        }
        __syncthreads();
    }

    float* sg = sm;
    #pragma unroll
    for (int mt = 0; mt < 2; mt++) {
        int row = wm * 32 + mt * 16 + (lane >> 2);
        int jj  = 2 * (lane & 3);
        sg[(wn * 64 + row) * 9 + jj]         = c[mt][0];
        sg[(wn * 64 + row) * 9 + jj + 1]     = c[mt][1];
        sg[(wn * 64 + row + 8) * 9 + jj]     = c[mt][2];
        sg[(wn * 64 + row + 8) * 9 + jj + 1] = c[mt][3];
    }
    __syncthreads();

    for (int q = tid; q < BATCH * 8; q += 256) {
        int m = q >> 3, jj = q & 7;
        float gi = sg[(0 * 64 + m) * 9 + jj];
        float gf = sg[(1 * 64 + m) * 9 + jj];
        float gg = sg[(2 * 64 + m) * 9 + jj];
        float go = sg[(3 * 64 + m) * 9 + jj];
        int cidx = m * HID + j0 + jj;
        float cold = g_c[cidx];
        float si = 1.f / (1.f + expf(-gi));
        float sf = 1.f / (1.f + expf(-gf));
        float so = 1.f / (1.f + expf(-go));
        float cn = sf * cold + si * tanhf(gg);
        float hn = so * tanhf(cn);
        g_c[cidx]      = cn;
        h_out[cidx]    = tfr(hn);   // next AR step's matmul input
        out_slot[cidx] = hn;        // full-precision output
    }
}

// ============================================================================
// launch
// ============================================================================
extern "C" void kernel_launch(void* const* d_in, const int* in_sizes, int n_in,
                              void* d_out, int out_size) {
    (void)in_sizes; (void)n_in; (void)out_size;
    const float* x    = (const float*)d_in[0];
    const float* hx0  = (const float*)d_in[1];
    const float* cx0  = (const float*)d_in[2];
    const float* W_ih = (const float*)d_in[3];
    const float* W_hh = (const float*)d_in[4];
    const float* b_ih = (const float*)d_in[5];
    const float* b_hh = (const float*)d_in[6];
    float* out = (float*)d_out;

    static bool attr_set = false;
    const int PERSIST_SMEM = (32 * WSTR + NSTG * 64 * ASTR) * 4;  // ~197 KB
    if (!attr_set) {
        cudaFuncSetAttribute(persist_kernel,
                             cudaFuncAttributeMaxDynamicSharedMemorySize, PERSIST_SMEM);
        attr_set = true;
    }

    // 1. prep: biases, Wsum, state init, barrier reset
    prep_kernel<<<(NG * HID + 255) / 256, 256>>>(W_ih, W_hh, b_ih, b_hh, hx0, cx0);

    // 2. precompute input projections for all 512 steps
    dim3 gA(NG / 64, MTOT / 128);
    gemmA_kernel<<<gA, 256>>>(x, W_ih);

    // 3. all 512 recurrent steps in one persistent launch
    persist_kernel<<<GRID, 256, PERSIST_SMEM>>>(W_hh);

    // 4. two autoregressive steps; write h to output
    for (int t = S_LEN; t < S_LEN + 2; t++)
        ar_step_kernel<<<HID / 8, 256>>>(t, out + (size_t)(t - S_LEN) * BATCH * HID);
}

// round 5
// speedup vs baseline: 1.0584x; 1.0584x over previous
#include <cuda_runtime.h>
#include <cstdint>
#include <cstddef>

#define S_LEN 512
#define BATCH 64
#define HID   1024
#define NG    4096            // 4*HID
#define MTOT  (S_LEN*BATCH)   // 32768
#define GRID  128             // persistent CTAs (HID/8)
#define NTHR  512             // persist threads (16 warps, 4/SMSP)
#define KCH   64              // k per chunk
#define NCHK  (HID/KCH)       // 16 chunks per step

// frag-major As: [2 bufs][4 mb][8 kk][33 lanes(pad)] float4
#define AS_KSTR   33                    // float4 units per kk row (32 lanes + 1 pad)
#define AS_BUFSZ  (4 * 8 * AS_KSTR)     // float4 units per buffer (1056)
// frag-major Ws: [4 wn][128 kglob8][32 lanes] float2
#define WS_ELEMS  (4 * 128 * 32)        // float2 units (16384)

// ---- scratch (device globals; no runtime allocation) ----
__device__ float g_gx[(size_t)MTOT * NG];   // precomputed x@W_ih^T + b
__device__ float g_h[2][BATCH * HID];       // double-buffered hidden state (tf32-rounded)
__device__ float g_c[BATCH * HID];          // cell state (fp32)
__device__ float g_b[NG];                   // b_ih + b_hh
__device__ float g_wsum[(size_t)NG * HID];  // W_ih + W_hh (AR steps)
__device__ unsigned g_bar;                  // grid barrier counter

// ---- tf32 helpers ----
__device__ __forceinline__ float tfr(float f) {
    unsigned u;
    asm("cvt.rna.tf32.f32 %0, %1;" : "=r"(u) : "f"(f));
    return __uint_as_float(u);
}

__device__ __forceinline__ void mma_tf32(float c[4], const unsigned a[4], const unsigned b[2]) {
    asm volatile(
        "mma.sync.aligned.m16n8k8.row.col.f32.tf32.tf32.f32 "
        "{%0,%1,%2,%3}, {%4,%5,%6,%7}, {%8,%9}, {%0,%1,%2,%3};\n"
        : "+f"(c[0]), "+f"(c[1]), "+f"(c[2]), "+f"(c[3])
        : "r"(a[0]), "r"(a[1]), "r"(a[2]), "r"(a[3]), "r"(b[0]), "r"(b[1]));
}

// ============================================================================
// prep: b = b_ih + b_hh ; Wsum = W_ih + W_hh ; h0 (tf32-rounded), c0 ; barrier=0
// ============================================================================
__global__ void prep_kernel(const float* __restrict__ W_ih, const float* __restrict__ W_hh,
                            const float* __restrict__ b_ih, const float* __restrict__ b_hh,
                            const float* __restrict__ hx0,  const float* __restrict__ cx0) {
    int idx = blockIdx.x * blockDim.x + threadIdx.x;
    if (idx == 0) g_bar = 0;
    if (idx < NG * HID) g_wsum[idx] = W_ih[idx] + W_hh[idx];
    if (idx < NG)       g_b[idx]    = b_ih[idx] + b_hh[idx];
    if (idx < BATCH * HID) {
        g_h[0][idx] = tfr(hx0[idx]);
        g_c[idx]    = cx0[idx];
    }
}

// ============================================================================
// gemmA: g_gx[M=32768, NG=4096] = X[M,1024] @ W_ih^T + b   (tf32 MMA)
// (unchanged; next optimization target)
// ============================================================================
__global__ __launch_bounds__(256) void gemmA_kernel(const float* __restrict__ X,
                                                    const float* __restrict__ W) {
    __shared__ float As[128][36];
    __shared__ float Bs[64][36];

    const int tid  = threadIdx.x;
    const int wid  = tid >> 5, lane = tid & 31;
    const int wm   = wid >> 1;
    const int wn   = wid & 1;
    const int m0   = blockIdx.y * 128;
    const int n0   = blockIdx.x * 64;

    const float* Ag = X + (size_t)m0 * HID;
    const float* Bg = W + (size_t)n0 * HID;

    float c[2][4][4];
    #pragma unroll
    for (int mt = 0; mt < 2; mt++)
        #pragma unroll
        for (int nt = 0; nt < 4; nt++)
            #pragma unroll
            for (int r = 0; r < 4; r++) c[mt][nt][r] = 0.f;

    float4 ra[4], rb[2];
    auto loadG = [&](int kc) {
        const int k0 = kc * 32;
        #pragma unroll
        for (int i = 0; i < 4; i++) {
            int l = tid + i * 256;
            int r = l >> 3, f = l & 7;
            ra[i] = *reinterpret_cast<const float4*>(Ag + (size_t)r * HID + k0 + f * 4);
        }
        #pragma unroll
        for (int i = 0; i < 2; i++) {
            int l = tid + i * 256;
            int r = l >> 3, f = l & 7;
            rb[i] = *reinterpret_cast<const float4*>(Bg + (size_t)r * HID + k0 + f * 4);
        }
    };

    loadG(0);
    for (int kc = 0; kc < 32; kc++) {
        #pragma unroll
        for (int i = 0; i < 4; i++) {
            int l = tid + i * 256;
            int r = l >> 3, f = l & 7;
            float4 v = ra[i];
            v.x = tfr(v.x); v.y = tfr(v.y); v.z = tfr(v.z); v.w = tfr(v.w);
            *reinterpret_cast<float4*>(&As[r][f * 4]) = v;
        }
        #pragma unroll
        for (int i = 0; i < 2; i++) {
            int l = tid + i * 256;
            int r = l >> 3, f = l & 7;
            float4 v = rb[i];
            v.x = tfr(v.x); v.y = tfr(v.y); v.z = tfr(v.z); v.w = tfr(v.w);
            *reinterpret_cast<float4*>(&Bs[r][f * 4]) = v;
        }
        __syncthreads();
        if (kc + 1 < 32) loadG(kc + 1);

        #pragma unroll
        for (int kk = 0; kk < 4; kk++) {
            const int k8 = kk * 8;
            unsigned a[2][4], b[4][2];
            #pragma unroll
            for (int mt = 0; mt < 2; mt++) {
                int r0 = wm * 32 + mt * 16 + (lane >> 2);
                a[mt][0] = __float_as_uint(As[r0][k8 + (lane & 3)]);
                a[mt][1] = __float_as_uint(As[r0 + 8][k8 + (lane & 3)]);
                a[mt][2] = __float_as_uint(As[r0][k8 + (lane & 3) + 4]);
                a[mt][3] = __float_as_uint(As[r0 + 8][k8 + (lane & 3) + 4]);
            }
            #pragma unroll
            for (int nt = 0; nt < 4; nt++) {
                int rn = wn * 32 + nt * 8 + (lane >> 2);
                b[nt][0] = __float_as_uint(Bs[rn][k8 + (lane & 3)]);
                b[nt][1] = __float_as_uint(Bs[rn][k8 + (lane & 3) + 4]);
            }
            #pragma unroll
            for (int mt = 0; mt < 2; mt++)
                #pragma unroll
                for (int nt = 0; nt < 4; nt++)
                    mma_tf32(c[mt][nt], a[mt], b[nt]);
        }
        __syncthreads();
    }

    #pragma unroll
    for (int mt = 0; mt < 2; mt++) {
        #pragma unroll
        for (int nt = 0; nt < 4; nt++) {
            int row = m0 + wm * 32 + mt * 16 + (lane >> 2);
            int col = n0 + wn * 32 + nt * 8 + 2 * (lane & 3);
            float b0 = g_b[col], b1 = g_b[col + 1];
            g_gx[(size_t)row * NG + col]           = c[mt][nt][0] + b0;
            g_gx[(size_t)row * NG + col + 1]       = c[mt][nt][1] + b1;
            g_gx[(size_t)(row + 8) * NG + col]     = c[mt][nt][2] + b0;
            g_gx[(size_t)(row + 8) * NG + col + 1] = c[mt][nt][3] + b1;
        }
    }
}

// ============================================================================
// persist: 512 steps. 128 CTAs x 512 threads (16 warps, warp tile 16x8).
// W slice pre-swizzled to b-frag-major SMEM (once); h staged per 64-col chunk
// into a-frag-major SMEM; 1 syncthreads per chunk; 2-iter LDG slack.
// ============================================================================
__global__ __launch_bounds__(NTHR) void persist_kernel(const float* __restrict__ Whh) {
    extern __shared__ float sm[];
    float*  WsF = sm;                              // float2-packed b-frags (as floats)
    float4* AsF = reinterpret_cast<float4*>(sm + WS_ELEMS * 2);  // 2 bufs of a-frags
    float*  sg  = reinterpret_cast<float*>(AsF);   // epilogue scratch (aliases AsF)

    const int tid = threadIdx.x, wid = tid >> 5, lane = tid & 31;
    const int wn = wid & 3;                        // gate index
    const int wm = wid >> 2;                       // m-tile 0..3 (rows 16wm..16wm+15)
    const int j0 = blockIdx.x * 8;

    // ---- prologue: W_hh slice -> b-frag-major SMEM (tf32) ----
    // source rows rn=0..31 map (gate=rn>>3, jj=rn&7); element k -> WsF slot.
    for (int i = tid; i < 32 * 256; i += NTHR) {
        int rn = i >> 8, f = i & 255;
        int gate = rn >> 3, jj = rn & 7;
        float4 v = *reinterpret_cast<const float4*>(
            Whh + (size_t)(gate * HID + j0 + jj) * HID + f * 4);
        float vv[4] = {tfr(v.x), tfr(v.y), tfr(v.z), tfr(v.w)};
        #pragma unroll
        for (int j = 0; j < 4; j++) {
            int k = f * 4 + j;
            int kg8  = k >> 3;
            int ln   = ((rn & 7) << 2) | (k & 3);
            int comp = (k >> 2) & 1;
            WsF[((gate * 128 + kg8) * 32 + ln) * 2 + comp] = vv[j];
        }
    }
    __syncthreads();

    const int rw   = lane >> 2;                    // frag row-within-8
    const int jcc  = 2 * (lane & 3);               // frag col base

    // staging geometry: r = tid>>3 (0..63), fs = tid&7; f in {fs, fs+8}
    const int srow = tid >> 3, sfs = tid & 7;
    const int smb  = srow >> 4, srw = srow & 15;

    for (int t = 0; t < S_LEN; t++) {
        const float* __restrict__ h_in  = g_h[t & 1];
        float*       __restrict__ h_out = g_h[(t + 1) & 1];
        const float* __restrict__ gx_t  = g_gx + (size_t)t * BATCH * NG;

        // prefetch gx (input projection + bias): 4 values matching c-frag
        float gxr[4];
        {
            int row = wm * 16 + rw;
            int n   = wn * HID + j0 + jcc;
            gxr[0] = gx_t[(size_t)row * NG + n];
            gxr[1] = gx_t[(size_t)row * NG + n + 1];
            gxr[2] = gx_t[(size_t)(row + 8) * NG + n];
            gxr[3] = gx_t[(size_t)(row + 8) * NG + n + 1];
        }

        float4 rbuf[2][2];
        auto loadChunk = [&](int kc, int rb) {
            const float* base = h_in + (size_t)srow * HID + kc * KCH;
            rbuf[rb][0] = *reinterpret_cast<const float4*>(base + sfs * 4);
            rbuf[rb][1] = *reinterpret_cast<const float4*>(base + (sfs + 8) * 4);
        };
        auto storeChunk = [&](int rb, int buf) {
            // scatter 8 scalars into a-frag-major layout (values already tf32)
            #pragma unroll
            for (int i = 0; i < 2; i++) {
                const float* v = reinterpret_cast<const float*>(&rbuf[rb][i]);
                int f = sfs + 8 * i;
                #pragma unroll
                for (int j = 0; j < 4; j++) {
                    int k = f * 4 + j;                  // 0..63 within chunk
                    int kk   = k >> 3;
                    int ln   = ((srw & 7) << 2) | (k & 3);
                    int comp = ((srw >> 3) & 1) | (((k >> 2) & 1) << 1);
                    reinterpret_cast<float*>(
                        &AsF[buf * AS_BUFSZ + (smb * 8 + kk) * AS_KSTR + ln])[comp] = v[j];
                }
            }
        };

        // pipeline fill: buf0 <- chunk0; rbuf holds chunks 1,2
        loadChunk(0, 0);
        loadChunk(1, 1);
        storeChunk(0, 0);
        loadChunk(2, 0);
        __syncthreads();

        float c[4] = {0.f, 0.f, 0.f, 0.f};

        for (int kc = 0; kc < NCHK; kc++) {
            const float4* Ab = AsF + (kc & 1) * AS_BUFSZ + wm * 8 * AS_KSTR;
            const float*  Wb = WsF + (wn * 128 + kc * 8) * 64;   // 32 lanes * 2 floats
            #pragma unroll
            for (int kk = 0; kk < 8; kk++) {
                float4 af = Ab[kk * AS_KSTR + lane];
                float2 bf = *reinterpret_cast<const float2*>(Wb + kk * 64 + lane * 2);
                unsigned a[4] = {__float_as_uint(af.x), __float_as_uint(af.y),
                                 __float_as_uint(af.z), __float_as_uint(af.w)};
                unsigned b[2] = {__float_as_uint(bf.x), __float_as_uint(bf.y)};
                mma_tf32(c, a, b);
            }
            if (kc + 1 < NCHK) storeChunk((kc + 1) & 1, (kc + 1) & 1);
            if (kc + 3 < NCHK) loadChunk(kc + 3, (kc + 1) & 1);
            __syncthreads();
        }

        // ---- gate exchange via SMEM (sg aliases AsF; all MMAs done) ----
        {
            int row = wm * 16 + rw;
            sg[(wn * 64 + row) * 9 + jcc]         = c[0] + gxr[0];
            sg[(wn * 64 + row) * 9 + jcc + 1]     = c[1] + gxr[1];
            sg[(wn * 64 + row + 8) * 9 + jcc]     = c[2] + gxr[2];
            sg[(wn * 64 + row + 8) * 9 + jcc + 1] = c[3] + gxr[3];
        }
        __syncthreads();

        // ---- elementwise cell update: 512 threads <-> 64x8 slice exactly ----
        {
            int m = tid >> 3, jj = tid & 7;
            float gi = sg[(0 * 64 + m) * 9 + jj];
            float gf = sg[(1 * 64 + m) * 9 + jj];
            float gg = sg[(2 * 64 + m) * 9 + jj];
            float go = sg[(3 * 64 + m) * 9 + jj];
            int cidx = m * HID + j0 + jj;
            float cold = g_c[cidx];
            float si = 1.f / (1.f + expf(-gi));
            float sf = 1.f / (1.f + expf(-gf));
            float so = 1.f / (1.f + expf(-go));
            float cn = sf * cold + si * tanhf(gg);
            float hn = so * tanhf(cn);
            g_c[cidx]   = cn;
            h_out[cidx] = tfr(hn);
        }

        // ---- grid barrier (monotonic counter; reset by prep each replay) ----
        __syncthreads();
        if (tid == 0) {
            __threadfence();
            atomicAdd(&g_bar, 1u);
            unsigned target = (unsigned)(t + 1) * GRID;
            while (*(volatile unsigned*)&g_bar < target) { }
            __threadfence();   // gpu-scope fence: invalidates this SM's L1
        }
        __syncthreads();
    }
}

// ============================================================================
// ar_step: autoregressive steps (gates = g_b + h @ Wsum^T); writes output
// ============================================================================
__global__ __launch_bounds__(256) void ar_step_kernel(int t, float* __restrict__ out_slot) {
    __shared__ float sm[64 * 36 + 32 * 36];
    float (*As)[36] = reinterpret_cast<float(*)[36]>(sm);
    float (*Bs)[36] = reinterpret_cast<float(*)[36]>(sm + 64 * 36);

    const int tid = threadIdx.x, wid = tid >> 5, lane = tid & 31;
    const int wn = wid & 3;
    const int wm = wid >> 2;
    const int j0 = blockIdx.x * 8;

    const float* __restrict__ h_in  = g_h[t & 1];
    float*       __restrict__ h_out = g_h[(t + 1) & 1];
    const float* __restrict__ W     = g_wsum;

    float c[2][4];
    #pragma unroll
    for (int mt = 0; mt < 2; mt++) {
        int jj = 2 * (lane & 3);
        int n  = wn * HID + j0 + jj;
        float b0 = g_b[n], b1 = g_b[n + 1];
        c[mt][0] = b0; c[mt][1] = b1;
        c[mt][2] = b0; c[mt][3] = b1;
    }

    float4 ra[2], rb;
    auto loadG = [&](int kc) {
        const int k0 = kc * 32;
        #pragma unroll
        for (int i = 0; i < 2; i++) {
            int l = tid + i * 256;
            int r = l >> 3, f = l & 7;
            ra[i] = *reinterpret_cast<const float4*>(h_in + (size_t)r * HID + k0 + f * 4);
        }
        {
            int r = tid >> 3, f = tid & 7;
            int gate = r >> 3, jj2 = r & 7;
            rb = *reinterpret_cast<const float4*>(
                W + (size_t)(gate * HID + j0 + jj2) * HID + k0 + f * 4);
        }
    };

    loadG(0);
    for (int kc = 0; kc < 32; kc++) {
        #pragma unroll
        for (int i = 0; i < 2; i++) {
            int l = tid + i * 256;
            int r = l >> 3, f = l & 7;
            float4 va = ra[i];
            va.x = tfr(va.x); va.y = tfr(va.y); va.z = tfr(va.z); va.w = tfr(va.w);
            *reinterpret_cast<float4*>(&As[r][f * 4]) = va;
        }
        {
            int r = tid >> 3, f = tid & 7;
            float4 vb = rb;
            vb.x = tfr(vb.x); vb.y = tfr(vb.y); vb.z = tfr(vb.z); vb.w = tfr(vb.w);
            *reinterpret_cast<float4*>(&Bs[r][f * 4]) = vb;
        }
        __syncthreads();
        if (kc + 1 < 32) loadG(kc + 1);

        #pragma unroll
        for (int kk = 0; kk < 4; kk++) {
            const int k8 = kk * 8;
            unsigned a[2][4], b[2];
            #pragma unroll
            for (int mt = 0; mt < 2; mt++) {
                int r0 = wm * 32 + mt * 16 + (lane >> 2);
                a[mt][0] = __float_as_uint(As[r0][k8 + (lane & 3)]);
                a[mt][1] = __float_as_uint(As[r0 + 8][k8 + (lane & 3)]);
                a[mt][2] = __float_as_uint(As[r0][k8 + (lane & 3) + 4]);
                a[mt][3] = __float_as_uint(As[r0 + 8][k8 + (lane & 3) + 4]);
            }
            {
                int rb2 = wn * 8 + (lane >> 2);
                b[0] = __float_as_uint(Bs[rb2][k8 + (lane & 3)]);
                b[1] = __float_as_uint(Bs[rb2][k8 + (lane & 3) + 4]);
            }
            #pragma unroll
            for (int mt = 0; mt < 2; mt++)
                mma_tf32(c[mt], a[mt], b);
        }
        __syncthreads();
    }

    float* sg = sm;
    #pragma unroll
    for (int mt = 0; mt < 2; mt++) {
        int row = wm * 32 + mt * 16 + (lane >> 2);
        int jj  = 2 * (lane & 3);
        sg[(wn * 64 + row) * 9 + jj]         = c[mt][0];
        sg[(wn * 64 + row) * 9 + jj + 1]     = c[mt][1];
        sg[(wn * 64 + row + 8) * 9 + jj]     = c[mt][2];
        sg[(wn * 64 + row + 8) * 9 + jj + 1] = c[mt][3];
    }
    __syncthreads();

    for (int q = tid; q < BATCH * 8; q += 256) {
        int m = q >> 3, jj = q & 7;
        float gi = sg[(0 * 64 + m) * 9 + jj];
        float gf = sg[(1 * 64 + m) * 9 + jj];
        float gg = sg[(2 * 64 + m) * 9 + jj];
        float go = sg[(3 * 64 + m) * 9 + jj];
        int cidx = m * HID + j0 + jj;
        float cold = g_c[cidx];
        float si = 1.f / (1.f + expf(-gi));
        float sf = 1.f / (1.f + expf(-gf));
        float so = 1.f / (1.f + expf(-go));
        float cn = sf * cold + si * tanhf(gg);
        float hn = so * tanhf(cn);
        g_c[cidx]      = cn;
        h_out[cidx]    = tfr(hn);
        out_slot[cidx] = hn;
    }
}

// ============================================================================
// launch
// ============================================================================
extern "C" void kernel_launch(void* const* d_in, const int* in_sizes, int n_in,
                              void* d_out, int out_size) {
    (void)in_sizes; (void)n_in; (void)out_size;
    const float* x    = (const float*)d_in[0];
    const float* hx0  = (const float*)d_in[1];
    const float* cx0  = (const float*)d_in[2];
    const float* W_ih = (const float*)d_in[3];
    const float* W_hh = (const float*)d_in[4];
    const float* b_ih = (const float*)d_in[5];
    const float* b_hh = (const float*)d_in[6];
    float* out = (float*)d_out;

    static bool attr_set = false;
    const int PERSIST_SMEM = (WS_ELEMS * 2 + 2 * AS_BUFSZ * 4) * 4;  // ~165 KB
    if (!attr_set) {
        cudaFuncSetAttribute(persist_kernel,
                             cudaFuncAttributeMaxDynamicSharedMemorySize, PERSIST_SMEM);
        attr_set = true;
    }

    // 1. prep: biases, Wsum, state init, barrier reset
    prep_kernel<<<(NG * HID + 255) / 256, 256>>>(W_ih, W_hh, b_ih, b_hh, hx0, cx0);

    // 2. precompute input projections for all 512 steps
    dim3 gA(NG / 64, MTOT / 128);
    gemmA_kernel<<<gA, 256>>>(x, W_ih);

    // 3. all 512 recurrent steps in one persistent launch
    persist_kernel<<<GRID, NTHR, PERSIST_SMEM>>>(W_hh);

    // 4. two autoregressive steps; write h to output
    for (int t = S_LEN; t < S_LEN + 2; t++)
        ar_step_kernel<<<HID / 8, 256>>>(t, out + (size_t)(t - S_LEN) * BATCH * HID);
}

// round 8
// speedup vs baseline: 2.0173x; 1.9060x over previous
#include <cuda_runtime.h>
#include <cstdint>
#include <cstddef>

#define S_LEN 512
#define BATCH 64
#define HID   1024
#define NG    4096            // 4*HID
#define MTOT  (S_LEN*BATCH)   // 32768
#define GRID  128             // persistent CTAs (HID/8)
#define PTHR  256             // 8 warps

#define BSTR  1028            // B SMEM row stride (floats); %32==4 -> conflict-free
#define AWS   36              // A chunk buffer row stride (floats); %32==4
#define AWF   (64 * AWS)      // floats per warp A buffer (2304)
#define SM_AB (32 * BSTR * 4) // byte offset of A buffers (131584)
#define SM_TOTAL (SM_AB + 8 * AWF * 4)   // 205312 bytes (~200.5KB)

// ---- scratch (device globals; no runtime allocation) ----
__device__ float g_gx[(size_t)MTOT * NG];   // precomputed x@W_ih^T + b
__device__ float g_h[2][BATCH * HID];       // double-buffered hidden state (tf32-rounded)
__device__ float g_c[BATCH * HID];          // cell state (fp32)
__device__ float g_b[NG];                   // b_ih + b_hh
__device__ float g_wsum[(size_t)NG * HID];  // W_ih + W_hh (AR steps)
__device__ unsigned g_bar;                  // grid barrier counter

// ---- tf32 helpers ----
__device__ __forceinline__ float tfr(float f) {
    unsigned u;
    asm("cvt.rna.tf32.f32 %0, %1;" : "=r"(u) : "f"(f));
    return __uint_as_float(u);
}

__device__ __forceinline__ void mma_tf32(float c[4], const unsigned a[4], const unsigned b[2]) {
    asm volatile(
        "mma.sync.aligned.m16n8k8.row.col.f32.tf32.tf32.f32 "
        "{%0,%1,%2,%3}, {%4,%5,%6,%7}, {%8,%9}, {%0,%1,%2,%3};\n"
        : "+f"(c[0]), "+f"(c[1]), "+f"(c[2]), "+f"(c[3])
        : "r"(a[0]), "r"(a[1]), "r"(a[2]), "r"(a[3]), "r"(b[0]), "r"(b[1]));
}

// ============================================================================
// prep: b = b_ih + b_hh ; Wsum ; h0 (tf32-rounded), c0 ; barrier=0
// ============================================================================
__global__ void prep_kernel(const float* __restrict__ W_ih, const float* __restrict__ W_hh,
                            const float* __restrict__ b_ih, const float* __restrict__ b_hh,
                            const float* __restrict__ hx0,  const float* __restrict__ cx0) {
    int idx = blockIdx.x * blockDim.x + threadIdx.x;
    if (idx == 0) g_bar = 0;
    if (idx < NG * HID) g_wsum[idx] = W_ih[idx] + W_hh[idx];
    if (idx < NG)       g_b[idx]    = b_ih[idx] + b_hh[idx];
    if (idx < BATCH * HID) {
        g_h[0][idx] = tfr(hx0[idx]);
        g_c[idx]    = cx0[idx];
    }
}

// ============================================================================
// gemmA: g_gx = X @ W_ih^T + b  (unchanged; verified)
// ============================================================================
__global__ __launch_bounds__(256) void gemmA_kernel(const float* __restrict__ X,
                                                    const float* __restrict__ W) {
    __shared__ float As[128][36];
    __shared__ float Bs[64][36];

    const int tid  = threadIdx.x;
    const int wid  = tid >> 5, lane = tid & 31;
    const int wm   = wid >> 1;
    const int wn   = wid & 1;
    const int m0   = blockIdx.y * 128;
    const int n0   = blockIdx.x * 64;

    const float* Ag = X + (size_t)m0 * HID;
    const float* Bg = W + (size_t)n0 * HID;

    float c[2][4][4];
    #pragma unroll
    for (int mt = 0; mt < 2; mt++)
        #pragma unroll
        for (int nt = 0; nt < 4; nt++)
            #pragma unroll
            for (int r = 0; r < 4; r++) c[mt][nt][r] = 0.f;

    float4 ra[4], rb[2];
    auto loadG = [&](int kc) {
        const int k0 = kc * 32;
        #pragma unroll
        for (int i = 0; i < 4; i++) {
            int l = tid + i * 256;
            int r = l >> 3, f = l & 7;
            ra[i] = *reinterpret_cast<const float4*>(Ag + (size_t)r * HID + k0 + f * 4);
        }
        #pragma unroll
        for (int i = 0; i < 2; i++) {
            int l = tid + i * 256;
            int r = l >> 3, f = l & 7;
            rb[i] = *reinterpret_cast<const float4*>(Bg + (size_t)r * HID + k0 + f * 4);
        }
    };

    loadG(0);
    for (int kc = 0; kc < 32; kc++) {
        #pragma unroll
        for (int i = 0; i < 4; i++) {
            int l = tid + i * 256;
            int r = l >> 3, f = l & 7;
            float4 v = ra[i];
            v.x = tfr(v.x); v.y = tfr(v.y); v.z = tfr(v.z); v.w = tfr(v.w);
            *reinterpret_cast<float4*>(&As[r][f * 4]) = v;
        }
        #pragma unroll
        for (int i = 0; i < 2; i++) {
            int l = tid + i * 256;
            int r = l >> 3, f = l & 7;
            float4 v = rb[i];
            v.x = tfr(v.x); v.y = tfr(v.y); v.z = tfr(v.z); v.w = tfr(v.w);
            *reinterpret_cast<float4*>(&Bs[r][f * 4]) = v;
        }
        __syncthreads();
        if (kc + 1 < 32) loadG(kc + 1);

        #pragma unroll
        for (int kk = 0; kk < 4; kk++) {
            const int k8 = kk * 8;
            unsigned a[2][4], b[4][2];
            #pragma unroll
            for (int mt = 0; mt < 2; mt++) {
                int r0 = wm * 32 + mt * 16 + (lane >> 2);
                a[mt][0] = __float_as_uint(As[r0][k8 + (lane & 3)]);
                a[mt][1] = __float_as_uint(As[r0 + 8][k8 + (lane & 3)]);
                a[mt][2] = __float_as_uint(As[r0][k8 + (lane & 3) + 4]);
                a[mt][3] = __float_as_uint(As[r0 + 8][k8 + (lane & 3) + 4]);
            }
            #pragma unroll
            for (int nt = 0; nt < 4; nt++) {
                int rn = wn * 32 + nt * 8 + (lane >> 2);
                b[nt][0] = __float_as_uint(Bs[rn][k8 + (lane & 3)]);
                b[nt][1] = __float_as_uint(Bs[rn][k8 + (lane & 3) + 4]);
            }
            #pragma unroll
            for (int mt = 0; mt < 2; mt++)
                #pragma unroll
                for (int nt = 0; nt < 4; nt++)
                    mma_tf32(c[mt][nt], a[mt], b[nt]);
        }
        __syncthreads();
    }

    #pragma unroll
    for (int mt = 0; mt < 2; mt++) {
        #pragma unroll
        for (int nt = 0; nt < 4; nt++) {
            int row = m0 + wm * 32 + mt * 16 + (lane >> 2);
            int col = n0 + wn * 32 + nt * 8 + 2 * (lane & 3);
            float b0 = g_b[col], b1 = g_b[col + 1];
            g_gx[(size_t)row * NG + col]           = c[mt][nt][0] + b0;
            g_gx[(size_t)row * NG + col + 1]       = c[mt][nt][1] + b1;
            g_gx[(size_t)(row + 8) * NG + col]     = c[mt][nt][2] + b0;
            g_gx[(size_t)(row + 8) * NG + col + 1] = c[mt][nt][3] + b1;
        }
    }
}

// ============================================================================
// persist: 512 steps, one launch, 128 CTAs x 256 threads.
// K-split: warp w computes full D[64,32] partial over K-slice [w*128,(w+1)*128),
// staging only its own h slice (zero block syncs in GEMM phase).
// B (W slice, 32x1024 tf32) resident in SMEM. Partials reduced via SMEM.
// ============================================================================
__global__ __launch_bounds__(PTHR) void persist_kernel(const float* __restrict__ Whh) {
    extern __shared__ float sm[];
    float* Bs    = sm;                 // [32][BSTR]
    float* AwAll = sm + 32 * BSTR;     // 8 x [64][AWS] (also partial buffers)

    const int tid = threadIdx.x, wid = tid >> 5, lane = tid & 31;
    const int j0 = blockIdx.x * 8;
    float* myA = AwAll + wid * AWF;
    const int kbase = wid * 128;

    // ---- prologue: W slice -> SMEM rows rn = gate*8+jj, tf32-rounded ----
    for (int i = tid; i < 32 * 256; i += PTHR) {      // 8192 float4 units
        int rn = i >> 8, f4 = i & 255;
        int gate = rn >> 3, jj = rn & 7;
        float4 v = *reinterpret_cast<const float4*>(
            Whh + (size_t)(gate * HID + j0 + jj) * HID + f4 * 4);
        v.x = tfr(v.x); v.y = tfr(v.y); v.z = tfr(v.z); v.w = tfr(v.w);
        *reinterpret_cast<float4*>(&Bs[rn * BSTR + f4 * 4]) = v;
    }
    __syncthreads();

    // reduce-phase position mapping (2 positions per thread)
    int   mm[2], jjv[2], base_pw[2][4];
    #pragma unroll
    for (int pi = 0; pi < 2; pi++) {
        int p  = tid + pi * 256;
        int mt = p >> 7, r = (p >> 5) & 3, ln = p & 31;
        mm[pi]  = mt * 16 + (ln >> 2) + 8 * (r >> 1);
        jjv[pi] = 2 * (ln & 3) + (r & 1);
        #pragma unroll
        for (int nt = 0; nt < 4; nt++)
            base_pw[pi][nt] = ((mt * 4 + nt) * 4 + r) * 32 + ln;
    }

    for (int t = 0; t < S_LEN; t++) {
        const float* __restrict__ h_in  = g_h[t & 1];
        float*       __restrict__ h_out = g_h[(t + 1) & 1];
        const float* __restrict__ gx_t  = g_gx + (size_t)t * BATCH * NG;

        // prefetch gx + c for the reduce phase (hidden under GEMM)
        float gxr[2][4], cr[2];
        #pragma unroll
        for (int pi = 0; pi < 2; pi++) {
            const float* gp = gx_t + (size_t)mm[pi] * NG + j0 + jjv[pi];
            gxr[pi][0] = gp[0 * HID];
            gxr[pi][1] = gp[1 * HID];
            gxr[pi][2] = gp[2 * HID];
            gxr[pi][3] = gp[3 * HID];
            cr[pi] = g_c[mm[pi] * HID + j0 + jjv[pi]];
        }

        // ---- per-warp GEMM over own K-slice; no block syncs ----
        float4 pf[16];
        auto ldchunk = [&](int cc) {
            const int k0 = kbase + cc * 32;
            #pragma unroll
            for (int i = 0; i < 16; i++) {
                int s = lane + 32 * i;
                pf[i] = *reinterpret_cast<const float4*>(
                    h_in + (size_t)(s >> 3) * HID + k0 + (s & 7) * 4);
            }
        };
        auto stchunk = [&]() {
            #pragma unroll
            for (int i = 0; i < 16; i++) {
                int s = lane + 32 * i;
                *reinterpret_cast<float4*>(&myA[(s >> 3) * AWS + (s & 7) * 4]) = pf[i];
            }
        };

        float acc[4][4][4];
        #pragma unroll
        for (int mt = 0; mt < 4; mt++)
            #pragma unroll
            for (int nt = 0; nt < 4; nt++)
                #pragma unroll
                for (int r = 0; r < 4; r++) acc[mt][nt][r] = 0.f;

        ldchunk(0);
        #pragma unroll
        for (int cc = 0; cc < 4; cc++) {
            stchunk();
            __syncwarp();
            if (cc < 3) ldchunk(cc + 1);

            #pragma unroll
            for (int k8i = 0; k8i < 4; k8i++) {
                const int kl = k8i * 8;                 // col in chunk buffer
                const int kg = kbase + cc * 32 + kl;    // global k for B
                unsigned a[4][4], b[4][2];
                #pragma unroll
                for (int mt = 0; mt < 4; mt++) {
                    int r0 = mt * 16 + (lane >> 2);
                    a[mt][0] = __float_as_uint(myA[r0 * AWS + kl + (lane & 3)]);
                    a[mt][1] = __float_as_uint(myA[(r0 + 8) * AWS + kl + (lane & 3)]);
                    a[mt][2] = __float_as_uint(myA[r0 * AWS + kl + (lane & 3) + 4]);
                    a[mt][3] = __float_as_uint(myA[(r0 + 8) * AWS + kl + (lane & 3) + 4]);
                }
                #pragma unroll
                for (int nt = 0; nt < 4; nt++) {
                    int rb = nt * 8 + (lane >> 2);
                    b[nt][0] = __float_as_uint(Bs[rb * BSTR + kg + (lane & 3)]);
                    b[nt][1] = __float_as_uint(Bs[rb * BSTR + kg + (lane & 3) + 4]);
                }
                #pragma unroll
                for (int mt = 0; mt < 4; mt++)
                    #pragma unroll
                    for (int nt = 0; nt < 4; nt++)
                        mma_tf32(acc[mt][nt], a[mt], b[nt]);
            }
            __syncwarp();
        }

        // ---- write partials into own buffer ----
        #pragma unroll
        for (int mt = 0; mt < 4; mt++)
            #pragma unroll
            for (int nt = 0; nt < 4; nt++)
                #pragma unroll
                for (int r = 0; r < 4; r++)
                    myA[((mt * 4 + nt) * 4 + r) * 32 + lane] = acc[mt][nt][r];
        __syncthreads();

        // ---- reduce across 8 warps + cell update (512 positions) ----
        #pragma unroll
        for (int pi = 0; pi < 2; pi++) {
            float g[4];
            #pragma unroll
            for (int nt = 0; nt < 4; nt++) {
                float s = 0.f;
                #pragma unroll
                for (int w = 0; w < 8; w++)
                    s += AwAll[w * AWF + base_pw[pi][nt]];
                g[nt] = s;
            }
            float gi = g[0] + gxr[pi][0];
            float gf = g[1] + gxr[pi][1];
            float gg = g[2] + gxr[pi][2];
            float go = g[3] + gxr[pi][3];
            float si = 1.f / (1.f + expf(-gi));
            float sf = 1.f / (1.f + expf(-gf));
            float so = 1.f / (1.f + expf(-go));
            float cn = sf * cr[pi] + si * tanhf(gg);
            float hn = so * tanhf(cn);
            int cidx = mm[pi] * HID + j0 + jjv[pi];
            g_c[cidx]   = cn;
            h_out[cidx] = tfr(hn);
        }
        __syncthreads();

        // ---- grid barrier (monotonic; reset by prep each replay) ----
        if (tid == 0) {
            __threadfence();
            atomicAdd(&g_bar, 1u);
            unsigned target = (unsigned)(t + 1) * GRID;
            while (*(volatile unsigned*)&g_bar < target) { }
            __threadfence();   // gpu-scope: invalidates this SM's L1
        }
        __syncthreads();
    }
}

// ============================================================================
// ar_step (unchanged): gates = g_b + h @ Wsum^T ; writes output
// ============================================================================
__global__ __launch_bounds__(256) void ar_step_kernel(int t, float* __restrict__ out_slot) {
    __shared__ float smem[64 * 36 + 32 * 36];
    float (*As)[36] = reinterpret_cast<float(*)[36]>(smem);
    float (*Bs)[36] = reinterpret_cast<float(*)[36]>(smem + 64 * 36);

    const int tid = threadIdx.x, wid = tid >> 5, lane = tid & 31;
    const int wn = wid & 3;
    const int wm = wid >> 2;
    const int j0 = blockIdx.x * 8;

    const float* __restrict__ h_in  = g_h[t & 1];
    float*       __restrict__ h_out = g_h[(t + 1) & 1];
    const float* __restrict__ W     = g_wsum;

    float c[2][4];
    #pragma unroll
    for (int mt = 0; mt < 2; mt++) {
        int jj = 2 * (lane & 3);
        int n  = wn * HID + j0 + jj;
        float b0 = g_b[n], b1 = g_b[n + 1];
        c[mt][0] = b0; c[mt][1] = b1;
        c[mt][2] = b0; c[mt][3] = b1;
    }

    float4 ra[2], rb;
    auto loadG = [&](int kc) {
        const int k0 = kc * 32;
        #pragma unroll
        for (int i = 0; i < 2; i++) {
            int l = tid + i * 256;
            int r = l >> 3, f = l & 7;
            ra[i] = *reinterpret_cast<const float4*>(h_in + (size_t)r * HID + k0 + f * 4);
        }
        {
            int r = tid >> 3, f = tid & 7;
            int gate = r >> 3, jj2 = r & 7;
            rb = *reinterpret_cast<const float4*>(
                W + (size_t)(gate * HID + j0 + jj2) * HID + k0 + f * 4);
        }
    };

    loadG(0);
    for (int kc = 0; kc < 32; kc++) {
        #pragma unroll
        for (int i = 0; i < 2; i++) {
            int l = tid + i * 256;
            int r = l >> 3, f = l & 7;
            float4 va = ra[i];
            va.x = tfr(va.x); va.y = tfr(va.y); va.z = tfr(va.z); va.w = tfr(va.w);
            *reinterpret_cast<float4*>(&As[r][f * 4]) = va;
        }
        {
            int r = tid >> 3, f = tid & 7;
            float4 vb = rb;
            vb.x = tfr(vb.x); vb.y = tfr(vb.y); vb.z = tfr(vb.z); vb.w = tfr(vb.w);
            *reinterpret_cast<float4*>(&Bs[r][f * 4]) = vb;
        }
        __syncthreads();
        if (kc + 1 < 32) loadG(kc + 1);

        #pragma unroll
        for (int kk = 0; kk < 4; kk++) {
            const int k8 = kk * 8;
            unsigned a[2][4], b[2];
            #pragma unroll
            for (int mt = 0; mt < 2; mt++) {
                int r0 = wm * 32 + mt * 16 + (lane >> 2);
                a[mt][0] = __float_as_uint(As[r0][k8 + (lane & 3)]);
                a[mt][1] = __float_as_uint(As[r0 + 8][k8 + (lane & 3)]);
                a[mt][2] = __float_as_uint(As[r0][k8 + (lane & 3) + 4]);
                a[mt][3] = __float_as_uint(As[r0 + 8][k8 + (lane & 3) + 4]);
            }
            {
                int rb2 = wn * 8 + (lane >> 2);
                b[0] = __float_as_uint(Bs[rb2][k8 + (lane & 3)]);
                b[1] = __float_as_uint(Bs[rb2][k8 + (lane & 3) + 4]);
            }
            #pragma unroll
            for (int mt = 0; mt < 2; mt++)
                mma_tf32(c[mt], a[mt], b);
        }
        __syncthreads();
    }

    float* sg = smem;
    #pragma unroll
    for (int mt = 0; mt < 2; mt++) {
        int row = wm * 32 + mt * 16 + (lane >> 2);
        int jj  = 2 * (lane & 3);
        sg[(wn * 64 + row) * 9 + jj]         = c[mt][0];
        sg[(wn * 64 + row) * 9 + jj + 1]     = c[mt][1];
        sg[(wn * 64 + row + 8) * 9 + jj]     = c[mt][2];
        sg[(wn * 64 + row + 8) * 9 + jj + 1] = c[mt][3];
    }
    __syncthreads();

    for (int q = tid; q < BATCH * 8; q += 256) {
        int m = q >> 3, jj = q & 7;
        float gi = sg[(0 * 64 + m) * 9 + jj];
        float gf = sg[(1 * 64 + m) * 9 + jj];
        float gg = sg[(2 * 64 + m) * 9 + jj];
        float go = sg[(3 * 64 + m) * 9 + jj];
        int cidx = m * HID + j0 + jj;
        float cold = g_c[cidx];
        float si = 1.f / (1.f + expf(-gi));
        float sf = 1.f / (1.f + expf(-gf));
        float so = 1.f / (1.f + expf(-go));
        float cn = sf * cold + si * tanhf(gg);
        float hn = so * tanhf(cn);
        g_c[cidx]      = cn;
        h_out[cidx]    = tfr(hn);
        out_slot[cidx] = hn;
    }
}

// ============================================================================
// launch
// ============================================================================
extern "C" void kernel_launch(void* const* d_in, const int* in_sizes, int n_in,
                              void* d_out, int out_size) {
    (void)in_sizes; (void)n_in; (void)out_size;
    const float* x    = (const float*)d_in[0];
    const float* hx0  = (const float*)d_in[1];
    const float* cx0  = (const float*)d_in[2];
    const float* W_ih = (const float*)d_in[3];
    const float* W_hh = (const float*)d_in[4];
    const float* b_ih = (const float*)d_in[5];
    const float* b_hh = (const float*)d_in[6];
    float* out = (float*)d_out;

    static bool attr_set = false;
    if (!attr_set) {
        cudaFuncSetAttribute(persist_kernel,
                             cudaFuncAttributeMaxDynamicSharedMemorySize, SM_TOTAL);
        attr_set = true;
    }

    prep_kernel<<<(NG * HID + 255) / 256, 256>>>(W_ih, W_hh, b_ih, b_hh, hx0, cx0);

    dim3 gA(NG / 64, MTOT / 128);
    gemmA_kernel<<<gA, 256>>>(x, W_ih);

    persist_kernel<<<GRID, PTHR, SM_TOTAL>>>(W_hh);

    for (int t = S_LEN; t < S_LEN + 2; t++)
        ar_step_kernel<<<HID / 8, 256>>>(t, out + (size_t)(t - S_LEN) * BATCH * HID);
}

// round 10
// speedup vs baseline: 2.0183x; 1.0005x over previous
#include <cuda_runtime.h>
#include <cstdint>
#include <cstddef>

#define S_LEN 512
#define BATCH 64
#define HID   1024
#define NG    4096            // 4*HID
#define MTOT  (S_LEN*BATCH)   // 32768
#define GRID  128             // persistent CTAs (HID/8)
#define PTHR  256             // 8 warps

#define BSTR  1028            // persist B SMEM row stride (floats); %32==4 -> conflict-free
#define AWS   36              // persist A chunk buffer row stride (floats); %32==4
#define AWF   (64 * AWS)      // floats per warp A buffer (2304)
#define SM_AB (32 * BSTR * 4) // byte offset of A buffers (131584)
#define SM_TOTAL (SM_AB + 8 * AWF * 4)   // 205312 bytes (~200.5KB)

// gemmA staging: 4 stages x (As[128][36] + Bs[64][36])
#define GA_STGF ((128 + 64) * 36)            // floats per stage (6912)
#define GA_SMEM (4 * GA_STGF * 4)            // 110592 bytes

// ---- scratch (device globals; no runtime allocation) ----
__device__ float g_gx[(size_t)MTOT * NG];   // precomputed x@W_ih^T + b
__device__ float g_h[2][BATCH * HID];       // double-buffered hidden state (tf32-rounded)
__device__ float g_c[BATCH * HID];          // cell state (fp32)
__device__ float g_b[NG];                   // b_ih + b_hh
__device__ float g_wsum[(size_t)NG * HID];  // W_ih + W_hh (AR steps)
__device__ unsigned g_bar;                  // grid barrier counter

// ---- tf32 helpers ----
__device__ __forceinline__ float tfr(float f) {
    unsigned u;
    asm("cvt.rna.tf32.f32 %0, %1;" : "=r"(u) : "f"(f));
    return __uint_as_float(u);
}

__device__ __forceinline__ void mma_tf32(float c[4], const unsigned a[4], const unsigned b[2]) {
    asm volatile(
        "mma.sync.aligned.m16n8k8.row.col.f32.tf32.tf32.f32 "
        "{%0,%1,%2,%3}, {%4,%5,%6,%7}, {%8,%9}, {%0,%1,%2,%3};\n"
        : "+f"(c[0]), "+f"(c[1]), "+f"(c[2]), "+f"(c[3])
        : "r"(a[0]), "r"(a[1]), "r"(a[2]), "r"(a[3]), "r"(b[0]), "r"(b[1]));
}

#define CP_ASYNC16(dst_u32, src) \
    asm volatile("cp.async.cg.shared.global [%0], [%1], 16;\n" :: "r"(dst_u32), "l"(src))
#define CP_COMMIT() asm volatile("cp.async.commit_group;\n" ::: "memory")
#define CP_WAIT2()  asm volatile("cp.async.wait_group 2;\n" ::: "memory")

// ============================================================================
// prep: b = b_ih + b_hh ; Wsum ; h0 (tf32-rounded), c0 ; barrier=0
// ============================================================================
__global__ void prep_kernel(const float* __restrict__ W_ih, const float* __restrict__ W_hh,
                            const float* __restrict__ b_ih, const float* __restrict__ b_hh,
                            const float* __restrict__ hx0,  const float* __restrict__ cx0) {
    int idx = blockIdx.x * blockDim.x + threadIdx.x;
    if (idx == 0) g_bar = 0;
    if (idx < NG * HID) g_wsum[idx] = W_ih[idx] + W_hh[idx];
    if (idx < NG)       g_b[idx]    = b_ih[idx] + b_hh[idx];
    if (idx < BATCH * HID) {
        g_h[0][idx] = tfr(hx0[idx]);
        g_c[idx]    = cx0[idx];
    }
}

// ============================================================================
// gemmA v2: g_gx = X @ W_ih^T + b ; 4-stage cp.async pipeline, 1 sync/chunk.
// Raw fp32 staged; RNA tf32 cvt after LDS -> numerics identical to v1.
// ============================================================================
__global__ __launch_bounds__(256) void gemmA_kernel(const float* __restrict__ X,
                                                    const float* __restrict__ W) {
    extern __shared__ float gsm[];

    const int tid  = threadIdx.x;
    const int wid  = tid >> 5, lane = tid & 31;
    const int wm   = wid >> 1;
    const int wn   = wid & 1;
    const int m0   = blockIdx.y * 128;
    const int n0   = blockIdx.x * 64;

    const float* Ag = X + (size_t)m0 * HID;
    const float* Bg = W + (size_t)n0 * HID;

    // per-thread staging geometry
    int ar_[4], af_[4], br_[2], bf_[2];
    #pragma unroll
    for (int i = 0; i < 4; i++) { int l = tid + i * 256; ar_[i] = l >> 3; af_[i] = l & 7; }
    #pragma unroll
    for (int i = 0; i < 2; i++) { int l = tid + i * 256; br_[i] = l >> 3; bf_[i] = l & 7; }

    auto issue = [&](int kc) {
        int s = kc & 3;
        float* as = gsm + s * GA_STGF;
        float* bs = as + 128 * 36;
        const int k0 = kc * 32;
        #pragma unroll
        for (int i = 0; i < 4; i++) {
            unsigned dst = (unsigned)__cvta_generic_to_shared(&as[ar_[i] * 36 + af_[i] * 4]);
            CP_ASYNC16(dst, Ag + (size_t)ar_[i] * HID + k0 + af_[i] * 4);
        }
        #pragma unroll
        for (int i = 0; i < 2; i++) {
            unsigned dst = (unsigned)__cvta_generic_to_shared(&bs[br_[i] * 36 + bf_[i] * 4]);
            CP_ASYNC16(dst, Bg + (size_t)br_[i] * HID + k0 + bf_[i] * 4);
        }
        CP_COMMIT();
    };

    float c[2][4][4];
    #pragma unroll
    for (int mt = 0; mt < 2; mt++)
        #pragma unroll
        for (int nt = 0; nt < 4; nt++)
            #pragma unroll
            for (int r = 0; r < 4; r++) c[mt][nt][r] = 0.f;

    issue(0); issue(1); issue(2);

    for (int kc = 0; kc < 32; kc++) {
        CP_WAIT2();                      // stage kc complete (<=2 newer outstanding)
        __syncthreads();                 // all threads' stage-kc data visible; frees (kc-1)&3
        if (kc + 3 < 32) issue(kc + 3);
        else CP_COMMIT();                // empty group keeps wait_group accounting exact

        const float* as = gsm + (kc & 3) * GA_STGF;
        const float* bs = as + 128 * 36;

        #pragma unroll
        for (int kk = 0; kk < 4; kk++) {
            const int k8 = kk * 8;
            unsigned a[2][4], b[4][2];
            #pragma unroll
            for (int mt = 0; mt < 2; mt++) {
                int r0 = wm * 32 + mt * 16 + (lane >> 2);
                a[mt][0] = __float_as_uint(tfr(as[r0 * 36 + k8 + (lane & 3)]));
                a[mt][1] = __float_as_uint(tfr(as[(r0 + 8) * 36 + k8 + (lane & 3)]));
                a[mt][2] = __float_as_uint(tfr(as[r0 * 36 + k8 + (lane & 3) + 4]));
                a[mt][3] = __float_as_uint(tfr(as[(r0 + 8) * 36 + k8 + (lane & 3) + 4]));
            }
            #pragma unroll
            for (int nt = 0; nt < 4; nt++) {
                int rn = wn * 32 + nt * 8 + (lane >> 2);
                b[nt][0] = __float_as_uint(tfr(bs[rn * 36 + k8 + (lane & 3)]));
                b[nt][1] = __float_as_uint(tfr(bs[rn * 36 + k8 + (lane & 3) + 4]));
            }
            #pragma unroll
            for (int mt = 0; mt < 2; mt++)
                #pragma unroll
                for (int nt = 0; nt < 4; nt++)
                    mma_tf32(c[mt][nt], a[mt], b[nt]);
        }
    }

    #pragma unroll
    for (int mt = 0; mt < 2; mt++) {
        #pragma unroll
        for (int nt = 0; nt < 4; nt++) {
            int row = m0 + wm * 32 + mt * 16 + (lane >> 2);
            int col = n0 + wn * 32 + nt * 8 + 2 * (lane & 3);
            float b0 = g_b[col], b1 = g_b[col + 1];
            g_gx[(size_t)row * NG + col]           = c[mt][nt][0] + b0;
            g_gx[(size_t)row * NG + col + 1]       = c[mt][nt][1] + b1;
            g_gx[(size_t)(row + 8) * NG + col]     = c[mt][nt][2] + b0;
            g_gx[(size_t)(row + 8) * NG + col + 1] = c[mt][nt][3] + b1;
        }
    }
}

// ============================================================================
// persist: 512 steps, one launch, 128 CTAs x 256 threads. K-split per warp.
// h loads via __ldcg (L2-direct). Grid barrier: R8-proven threadfence form.
// ============================================================================
__global__ __launch_bounds__(PTHR) void persist_kernel(const float* __restrict__ Whh) {
    extern __shared__ float sm[];
    float* Bs    = sm;                 // [32][BSTR]
    float* AwAll = sm + 32 * BSTR;     // 8 x [64][AWS] (also partial buffers)

    const int tid = threadIdx.x, wid = tid >> 5, lane = tid & 31;
    const int j0 = blockIdx.x * 8;
    float* myA = AwAll + wid * AWF;
    const int kbase = wid * 128;

    // ---- prologue: W slice -> SMEM rows rn = gate*8+jj, tf32-rounded ----
    for (int i = tid; i < 32 * 256; i += PTHR) {      // 8192 float4 units
        int rn = i >> 8, f4 = i & 255;
        int gate = rn >> 3, jj = rn & 7;
        float4 v = *reinterpret_cast<const float4*>(
            Whh + (size_t)(gate * HID + j0 + jj) * HID + f4 * 4);
        v.x = tfr(v.x); v.y = tfr(v.y); v.z = tfr(v.z); v.w = tfr(v.w);
        *reinterpret_cast<float4*>(&Bs[rn * BSTR + f4 * 4]) = v;
    }
    __syncthreads();

    // reduce-phase position mapping (2 positions per thread)
    int   mm[2], jjv[2], base_pw[2][4];
    #pragma unroll
    for (int pi = 0; pi < 2; pi++) {
        int p  = tid + pi * 256;
        int mt = p >> 7, r = (p >> 5) & 3, ln = p & 31;
        mm[pi]  = mt * 16 + (ln >> 2) + 8 * (r >> 1);
        jjv[pi] = 2 * (ln & 3) + (r & 1);
        #pragma unroll
        for (int nt = 0; nt < 4; nt++)
            base_pw[pi][nt] = ((mt * 4 + nt) * 4 + r) * 32 + ln;
    }

    for (int t = 0; t < S_LEN; t++) {
        const float* __restrict__ h_in  = g_h[t & 1];
        float*       __restrict__ h_out = g_h[(t + 1) & 1];
        const float* __restrict__ gx_t  = g_gx + (size_t)t * BATCH * NG;

        // prefetch gx + c for the reduce phase (hidden under GEMM)
        float gxr[2][4], cr[2];
        #pragma unroll
        for (int pi = 0; pi < 2; pi++) {
            const float* gp = gx_t + (size_t)mm[pi] * NG + j0 + jjv[pi];
            gxr[pi][0] = gp[0 * HID];
            gxr[pi][1] = gp[1 * HID];
            gxr[pi][2] = gp[2 * HID];
            gxr[pi][3] = gp[3 * HID];
            cr[pi] = g_c[mm[pi] * HID + j0 + jjv[pi]];
        }

        // ---- per-warp GEMM over own K-slice; no block syncs ----
        float4 pf[16];
        auto ldchunk = [&](int cc) {
            const int k0 = kbase + cc * 32;
            #pragma unroll
            for (int i = 0; i < 16; i++) {
                int s = lane + 32 * i;
                pf[i] = __ldcg(reinterpret_cast<const float4*>(
                    h_in + (size_t)(s >> 3) * HID + k0 + (s & 7) * 4));
            }
        };
        auto stchunk = [&]() {
            #pragma unroll
            for (int i = 0; i < 16; i++) {
                int s = lane + 32 * i;
                *reinterpret_cast<float4*>(&myA[(s >> 3) * AWS + (s & 7) * 4]) = pf[i];
            }
        };

        float acc[4][4][4];
        #pragma unroll
        for (int mt = 0; mt < 4; mt++)
            #pragma unroll
            for (int nt = 0; nt < 4; nt++)
                #pragma unroll
                for (int r = 0; r < 4; r++) acc[mt][nt][r] = 0.f;

        ldchunk(0);
        #pragma unroll
        for (int cc = 0; cc < 4; cc++) {
            stchunk();
            __syncwarp();
            if (cc < 3) ldchunk(cc + 1);

            #pragma unroll
            for (int k8i = 0; k8i < 4; k8i++) {
                const int kl = k8i * 8;                 // col in chunk buffer
                const int kg = kbase + cc * 32 + kl;    // global k for B
                unsigned a[4][4], b[4][2];
                #pragma unroll
                for (int mt = 0; mt < 4; mt++) {
                    int r0 = mt * 16 + (lane >> 2);
                    a[mt][0] = __float_as_uint(myA[r0 * AWS + kl + (lane & 3)]);
                    a[mt][1] = __float_as_uint(myA[(r0 + 8) * AWS + kl + (lane & 3)]);
                    a[mt][2] = __float_as_uint(myA[r0 * AWS + kl + (lane & 3) + 4]);
                    a[mt][3] = __float_as_uint(myA[(r0 + 8) * AWS + kl + (lane & 3) + 4]);
                }
                #pragma unroll
                for (int nt = 0; nt < 4; nt++) {
                    int rb = nt * 8 + (lane >> 2);
                    b[nt][0] = __float_as_uint(Bs[rb * BSTR + kg + (lane & 3)]);
                    b[nt][1] = __float_as_uint(Bs[rb * BSTR + kg + (lane & 3) + 4]);
                }
                #pragma unroll
                for (int mt = 0; mt < 4; mt++)
                    #pragma unroll
                    for (int nt = 0; nt < 4; nt++)
                        mma_tf32(acc[mt][nt], a[mt], b[nt]);
            }
            __syncwarp();
        }

        // ---- write partials into own buffer ----
        #pragma unroll
        for (int mt = 0; mt < 4; mt++)
            #pragma unroll
            for (int nt = 0; nt < 4; nt++)
                #pragma unroll
                for (int r = 0; r < 4; r++)
                    myA[((mt * 4 + nt) * 4 + r) * 32 + lane] = acc[mt][nt][r];
        __syncthreads();

        // ---- reduce across 8 warps + cell update (512 positions) ----
        #pragma unroll
        for (int pi = 0; pi < 2; pi++) {
            float g[4];
            #pragma unroll
            for (int nt = 0; nt < 4; nt++) {
                float s = 0.f;
                #pragma unroll
                for (int w = 0; w < 8; w++)
                    s += AwAll[w * AWF + base_pw[pi][nt]];
                g[nt] = s;
            }
            float gi = g[0] + gxr[pi][0];
            float gf = g[1] + gxr[pi][1];
            float gg = g[2] + gxr[pi][2];
            float go = g[3] + gxr[pi][3];
            float si = 1.f / (1.f + expf(-gi));
            float sf = 1.f / (1.f + expf(-gf));
            float so = 1.f / (1.f + expf(-go));
            float cn = sf * cr[pi] + si * tanhf(gg);
            float hn = so * tanhf(cn);
            int cidx = mm[pi] * HID + j0 + jjv[pi];
            g_c[cidx]   = cn;
            h_out[cidx] = tfr(hn);
        }
        __syncthreads();

        // ---- grid barrier (R8-proven form: monotonic counter + threadfence) ----
        if (tid == 0) {
            __threadfence();
            atomicAdd(&g_bar, 1u);
            unsigned target = (unsigned)(t + 1) * GRID;
            while (*(volatile unsigned*)&g_bar < target) { }
            __threadfence();
        }
        __syncthreads();
    }
}

// ============================================================================
// ar_step (unchanged): gates = g_b + h @ Wsum^T ; writes output
// ============================================================================
__global__ __launch_bounds__(256) void ar_step_kernel(int t, float* __restrict__ out_slot) {
    __shared__ float smem[64 * 36 + 32 * 36];
    float (*As)[36] = reinterpret_cast<float(*)[36]>(smem);
    float (*Bs)[36] = reinterpret_cast<float(*)[36]>(smem + 64 * 36);

    const int tid = threadIdx.x, wid = tid >> 5, lane = tid & 31;
    const int wn = wid & 3;
    const int wm = wid >> 2;
    const int j0 = blockIdx.x * 8;

    const float* __restrict__ h_in  = g_h[t & 1];
    float*       __restrict__ h_out = g_h[(t + 1) & 1];
    const float* __restrict__ W     = g_wsum;

    float c[2][4];
    #pragma unroll
    for (int mt = 0; mt < 2; mt++) {
        int jj = 2 * (lane & 3);
        int n  = wn * HID + j0 + jj;
        float b0 = g_b[n], b1 = g_b[n + 1];
        c[mt][0] = b0; c[mt][1] = b1;
        c[mt][2] = b0; c[mt][3] = b1;
    }

    float4 ra[2], rb;
    auto loadG = [&](int kc) {
        const int k0 = kc * 32;
        #pragma unroll
        for (int i = 0; i < 2; i++) {
            int l = tid + i * 256;
            int r = l >> 3, f = l & 7;
            ra[i] = *reinterpret_cast<const float4*>(h_in + (size_t)r * HID + k0 + f * 4);
        }
        {
            int r = tid >> 3, f = tid & 7;
            int gate = r >> 3, jj2 = r & 7;
            rb = *reinterpret_cast<const float4*>(
                W + (size_t)(gate * HID + j0 + jj2) * HID + k0 + f * 4);
        }
    };

    loadG(0);
    for (int kc = 0; kc < 32; kc++) {
        #pragma unroll
        for (int i = 0; i < 2; i++) {
            int l = tid + i * 256;
            int r = l >> 3, f = l & 7;
            float4 va = ra[i];
            va.x = tfr(va.x); va.y = tfr(va.y); va.z = tfr(va.z); va.w = tfr(va.w);
            *reinterpret_cast<float4*>(&As[r][f * 4]) = va;
        }
        {
            int r = tid >> 3, f = tid & 7;
            float4 vb = rb;
            vb.x = tfr(vb.x); vb.y = tfr(vb.y); vb.z = tfr(vb.z); vb.w = tfr(vb.w);
            *reinterpret_cast<float4*>(&Bs[r][f * 4]) = vb;
        }
        __syncthreads();
        if (kc + 1 < 32) loadG(kc + 1);

        #pragma unroll
        for (int kk = 0; kk < 4; kk++) {
            const int k8 = kk * 8;
            unsigned a[2][4], b[2];
            #pragma unroll
            for (int mt = 0; mt < 2; mt++) {
                int r0 = wm * 32 + mt * 16 + (lane >> 2);
                a[mt][0] = __float_as_uint(As[r0][k8 + (lane & 3)]);
                a[mt][1] = __float_as_uint(As[r0 + 8][k8 + (lane & 3)]);
                a[mt][2] = __float_as_uint(As[r0][k8 + (lane & 3) + 4]);
                a[mt][3] = __float_as_uint(As[r0 + 8][k8 + (lane & 3) + 4]);
            }
            {
                int rb2 = wn * 8 + (lane >> 2);
                b[0] = __float_as_uint(Bs[rb2][k8 + (lane & 3)]);
                b[1] = __float_as_uint(Bs[rb2][k8 + (lane & 3) + 4]);
            }
            #pragma unroll
            for (int mt = 0; mt < 2; mt++)
                mma_tf32(c[mt], a[mt], b);
        }
        __syncthreads();
    }

    float* sg = smem;
    #pragma unroll
    for (int mt = 0; mt < 2; mt++) {
        int row = wm * 32 + mt * 16 + (lane >> 2);
        int jj  = 2 * (lane & 3);
        sg[(wn * 64 + row) * 9 + jj]         = c[mt][0];
        sg[(wn * 64 + row) * 9 + jj + 1]     = c[mt][1];
        sg[(wn * 64 + row + 8) * 9 + jj]     = c[mt][2];
        sg[(wn * 64 + row + 8) * 9 + jj + 1] = c[mt][3];
    }
    __syncthreads();

    for (int q = tid; q < BATCH * 8; q += 256) {
        int m = q >> 3, jj = q & 7;
        float gi = sg[(0 * 64 + m) * 9 + jj];
        float gf = sg[(1 * 64 + m) * 9 + jj];
        float gg = sg[(2 * 64 + m) * 9 + jj];
        float go = sg[(3 * 64 + m) * 9 + jj];
        int cidx = m * HID + j0 + jj;
        float cold = g_c[cidx];
        float si = 1.f / (1.f + expf(-gi));
        float sf = 1.f / (1.f + expf(-gf));
        float so = 1.f / (1.f + expf(-go));
        float cn = sf * cold + si * tanhf(gg);
        float hn = so * tanhf(cn);
        g_c[cidx]      = cn;
        h_out[cidx]    = tfr(hn);
        out_slot[cidx] = hn;
    }
}

// ============================================================================
// launch
// ============================================================================
extern "C" void kernel_launch(void* const* d_in, const int* in_sizes, int n_in,
                              void* d_out, int out_size) {
    (void)in_sizes; (void)n_in; (void)out_size;
    const float* x    = (const float*)d_in[0];
    const float* hx0  = (const float*)d_in[1];
    const float* cx0  = (const float*)d_in[2];
    const float* W_ih = (const float*)d_in[3];
    const float* W_hh = (const float*)d_in[4];
    const float* b_ih = (const float*)d_in[5];
    const float* b_hh = (const float*)d_in[6];
    float* out = (float*)d_out;

    static bool attr_set = false;
    if (!attr_set) {
        cudaFuncSetAttribute(persist_kernel,
                             cudaFuncAttributeMaxDynamicSharedMemorySize, SM_TOTAL);
        cudaFuncSetAttribute(gemmA_kernel,
                             cudaFuncAttributeMaxDynamicSharedMemorySize, GA_SMEM);
        attr_set = true;
    }

    prep_kernel<<<(NG * HID + 255) / 256, 256>>>(W_ih, W_hh, b_ih, b_hh, hx0, cx0);

    dim3 gA(NG / 64, MTOT / 128);
    gemmA_kernel<<<gA, 256, GA_SMEM>>>(x, W_ih);

    persist_kernel<<<GRID, PTHR, SM_TOTAL>>>(W_hh);

    for (int t = S_LEN; t < S_LEN + 2; t++)
        ar_step_kernel<<<HID / 8, 256>>>(t, out + (size_t)(t - S_LEN) * BATCH * HID);
}

// round 11
// speedup vs baseline: 2.1065x; 1.0437x over previous
#include <cuda_runtime.h>
#include <cstdint>
#include <cstddef>

#define S_LEN 512
#define BATCH 64
#define HID   1024
#define NG    4096            // 4*HID
#define MTOT  (S_LEN*BATCH)   // 32768
#define GRID  128             // persistent CTAs (HID/8)
#define PTHR  256             // 8 warps

#define BSTR  1028            // persist B SMEM row stride (floats); %32==4 -> conflict-free
#define AWS   36              // persist A chunk buffer row stride (floats); %32==4
#define AWF   (64 * AWS)      // floats per warp A buffer (2304)
#define SM_AB (32 * BSTR * 4) // byte offset of A buffers (131584)
#define SM_TOTAL (SM_AB + 8 * AWF * 4)   // 205312 bytes (~200.5KB)

// gemmA v3: CTA tile 128x128, 4 stages x (As[128][36] + Bs[128][36])
#define GA_STGF ((128 + 128) * 36)           // floats per stage (9216)
#define GA_SMEM (4 * GA_STGF * 4)            // 147456 bytes

// ---- scratch (device globals; no runtime allocation) ----
__device__ float g_gx[(size_t)MTOT * NG];   // precomputed x@W_ih^T + b
__device__ float g_h[2][BATCH * HID];       // double-buffered hidden state (tf32-rounded)
__device__ float g_c[BATCH * HID];          // cell state (fp32)
__device__ float g_b[NG];                   // b_ih + b_hh
__device__ float g_wsum[(size_t)NG * HID];  // W_ih + W_hh (AR steps)
__device__ unsigned g_bar;                  // grid barrier counter

// ---- tf32 helpers ----
__device__ __forceinline__ float tfr(float f) {
    unsigned u;
    asm("cvt.rna.tf32.f32 %0, %1;" : "=r"(u) : "f"(f));
    return __uint_as_float(u);
}

__device__ __forceinline__ void mma_tf32(float c[4], const unsigned a[4], const unsigned b[2]) {
    asm volatile(
        "mma.sync.aligned.m16n8k8.row.col.f32.tf32.tf32.f32 "
        "{%0,%1,%2,%3}, {%4,%5,%6,%7}, {%8,%9}, {%0,%1,%2,%3};\n"
        : "+f"(c[0]), "+f"(c[1]), "+f"(c[2]), "+f"(c[3])
        : "r"(a[0]), "r"(a[1]), "r"(a[2]), "r"(a[3]), "r"(b[0]), "r"(b[1]));
}

#define CP_ASYNC16(dst_u32, src) \
    asm volatile("cp.async.cg.shared.global [%0], [%1], 16;\n" :: "r"(dst_u32), "l"(src))
#define CP_COMMIT() asm volatile("cp.async.commit_group;\n" ::: "memory")
#define CP_WAIT2()  asm volatile("cp.async.wait_group 2;\n" ::: "memory")

// ============================================================================
// prep: b = b_ih + b_hh ; Wsum ; h0 (tf32-rounded), c0 ; barrier=0
// ============================================================================
__global__ void prep_kernel(const float* __restrict__ W_ih, const float* __restrict__ W_hh,
                            const float* __restrict__ b_ih, const float* __restrict__ b_hh,
                            const float* __restrict__ hx0,  const float* __restrict__ cx0) {
    int idx = blockIdx.x * blockDim.x + threadIdx.x;
    if (idx == 0) g_bar = 0;
    if (idx < NG * HID) g_wsum[idx] = W_ih[idx] + W_hh[idx];
    if (idx < NG)       g_b[idx]    = b_ih[idx] + b_hh[idx];
    if (idx < BATCH * HID) {
        g_h[0][idx] = tfr(hx0[idx]);
        g_c[idx]    = cx0[idx];
    }
}

// ============================================================================
// gemmA v3: g_gx = X @ W_ih^T + b ; CTA tile 128x128 (halves L2 traffic),
// 8 warps (2M x 4N), warp tile 64x32, 4-stage cp.async, 1 sync/chunk.
// Raw fp32 staged; RNA tf32 cvt post-LDS -> numerics identical.
// ============================================================================
__global__ __launch_bounds__(256) void gemmA_kernel(const float* __restrict__ X,
                                                    const float* __restrict__ W) {
    extern __shared__ float gsm[];

    const int tid  = threadIdx.x;
    const int wid  = tid >> 5, lane = tid & 31;
    const int wm   = wid >> 2;      // 0..1  (64-row block)
    const int wn   = wid & 3;       // 0..3  (32-col block)
    const int m0   = blockIdx.y * 128;
    const int n0   = blockIdx.x * 128;

    const float* Ag = X + (size_t)m0 * HID;
    const float* Bg = W + (size_t)n0 * HID;

    // per-thread staging geometry: A 4x f4 (128 rows), B 4x f4 (128 rows)
    int ar_[4], af_[4];
    #pragma unroll
    for (int i = 0; i < 4; i++) { int l = tid + i * 256; ar_[i] = l >> 3; af_[i] = l & 7; }

    auto issue = [&](int kc) {
        int s = kc & 3;
        float* as = gsm + s * GA_STGF;
        float* bs = as + 128 * 36;
        const int k0 = kc * 32;
        #pragma unroll
        for (int i = 0; i < 4; i++) {
            unsigned dst = (unsigned)__cvta_generic_to_shared(&as[ar_[i] * 36 + af_[i] * 4]);
            CP_ASYNC16(dst, Ag + (size_t)ar_[i] * HID + k0 + af_[i] * 4);
        }
        #pragma unroll
        for (int i = 0; i < 4; i++) {
            unsigned dst = (unsigned)__cvta_generic_to_shared(&bs[ar_[i] * 36 + af_[i] * 4]);
            CP_ASYNC16(dst, Bg + (size_t)ar_[i] * HID + k0 + af_[i] * 4);
        }
        CP_COMMIT();
    };

    float c[4][4][4];
    #pragma unroll
    for (int mt = 0; mt < 4; mt++)
        #pragma unroll
        for (int nt = 0; nt < 4; nt++)
            #pragma unroll
            for (int r = 0; r < 4; r++) c[mt][nt][r] = 0.f;

    issue(0); issue(1); issue(2);

    for (int kc = 0; kc < 32; kc++) {
        CP_WAIT2();                      // stage kc complete (<=2 newer outstanding)
        __syncthreads();                 // data visible to all; frees stage (kc-1)&3
        if (kc + 3 < 32) issue(kc + 3);
        else CP_COMMIT();                // empty group keeps wait_group accounting exact

        const float* as = gsm + (kc & 3) * GA_STGF;
        const float* bs = as + 128 * 36;

        #pragma unroll
        for (int kk = 0; kk < 4; kk++) {
            const int k8 = kk * 8;
            unsigned a[4][4], b[4][2];
            #pragma unroll
            for (int mt = 0; mt < 4; mt++) {
                int r0 = wm * 64 + mt * 16 + (lane >> 2);
                a[mt][0] = __float_as_uint(tfr(as[r0 * 36 + k8 + (lane & 3)]));
                a[mt][1] = __float_as_uint(tfr(as[(r0 + 8) * 36 + k8 + (lane & 3)]));
                a[mt][2] = __float_as_uint(tfr(as[r0 * 36 + k8 + (lane & 3) + 4]));
                a[mt][3] = __float_as_uint(tfr(as[(r0 + 8) * 36 + k8 + (lane & 3) + 4]));
            }
            #pragma unroll
            for (int nt = 0; nt < 4; nt++) {
                int rn = wn * 32 + nt * 8 + (lane >> 2);
                b[nt][0] = __float_as_uint(tfr(bs[rn * 36 + k8 + (lane & 3)]));
                b[nt][1] = __float_as_uint(tfr(bs[rn * 36 + k8 + (lane & 3) + 4]));
            }
            #pragma unroll
            for (int mt = 0; mt < 4; mt++)
                #pragma unroll
                for (int nt = 0; nt < 4; nt++)
                    mma_tf32(c[mt][nt], a[mt], b[nt]);
        }
    }

    #pragma unroll
    for (int mt = 0; mt < 4; mt++) {
        #pragma unroll
        for (int nt = 0; nt < 4; nt++) {
            int row = m0 + wm * 64 + mt * 16 + (lane >> 2);
            int col = n0 + wn * 32 + nt * 8 + 2 * (lane & 3);
            float b0 = g_b[col], b1 = g_b[col + 1];
            g_gx[(size_t)row * NG + col]           = c[mt][nt][0] + b0;
            g_gx[(size_t)row * NG + col + 1]       = c[mt][nt][1] + b1;
            g_gx[(size_t)(row + 8) * NG + col]     = c[mt][nt][2] + b0;
            g_gx[(size_t)(row + 8) * NG + col + 1] = c[mt][nt][3] + b1;
        }
    }
}

// ============================================================================
// persist: 512 steps, one launch, 128 CTAs x 256 threads. K-split per warp.
// (frozen from R10-passing version for clean attribution)
// ============================================================================
__global__ __launch_bounds__(PTHR) void persist_kernel(const float* __restrict__ Whh) {
    extern __shared__ float sm[];
    float* Bs    = sm;                 // [32][BSTR]
    float* AwAll = sm + 32 * BSTR;     // 8 x [64][AWS] (also partial buffers)

    const int tid = threadIdx.x, wid = tid >> 5, lane = tid & 31;
    const int j0 = blockIdx.x * 8;
    float* myA = AwAll + wid * AWF;
    const int kbase = wid * 128;

    // ---- prologue: W slice -> SMEM rows rn = gate*8+jj, tf32-rounded ----
    for (int i = tid; i < 32 * 256; i += PTHR) {      // 8192 float4 units
        int rn = i >> 8, f4 = i & 255;
        int gate = rn >> 3, jj = rn & 7;
        float4 v = *reinterpret_cast<const float4*>(
            Whh + (size_t)(gate * HID + j0 + jj) * HID + f4 * 4);
        v.x = tfr(v.x); v.y = tfr(v.y); v.z = tfr(v.z); v.w = tfr(v.w);
        *reinterpret_cast<float4*>(&Bs[rn * BSTR + f4 * 4]) = v;
    }
    __syncthreads();

    // reduce-phase position mapping (2 positions per thread)
    int   mm[2], jjv[2], base_pw[2][4];
    #pragma unroll
    for (int pi = 0; pi < 2; pi++) {
        int p  = tid + pi * 256;
        int mt = p >> 7, r = (p >> 5) & 3, ln = p & 31;
        mm[pi]  = mt * 16 + (ln >> 2) + 8 * (r >> 1);
        jjv[pi] = 2 * (ln & 3) + (r & 1);
        #pragma unroll
        for (int nt = 0; nt < 4; nt++)
            base_pw[pi][nt] = ((mt * 4 + nt) * 4 + r) * 32 + ln;
    }

    for (int t = 0; t < S_LEN; t++) {
        const float* __restrict__ h_in  = g_h[t & 1];
        float*       __restrict__ h_out = g_h[(t + 1) & 1];
        const float* __restrict__ gx_t  = g_gx + (size_t)t * BATCH * NG;

        // prefetch gx + c for the reduce phase (hidden under GEMM)
        float gxr[2][4], cr[2];
        #pragma unroll
        for (int pi = 0; pi < 2; pi++) {
            const float* gp = gx_t + (size_t)mm[pi] * NG + j0 + jjv[pi];
            gxr[pi][0] = gp[0 * HID];
            gxr[pi][1] = gp[1 * HID];
            gxr[pi][2] = gp[2 * HID];
            gxr[pi][3] = gp[3 * HID];
            cr[pi] = g_c[mm[pi] * HID + j0 + jjv[pi]];
        }

        // ---- per-warp GEMM over own K-slice; no block syncs ----
        float4 pf[16];
        auto ldchunk = [&](int cc) {
            const int k0 = kbase + cc * 32;
            #pragma unroll
            for (int i = 0; i < 16; i++) {
                int s = lane + 32 * i;
                pf[i] = __ldcg(reinterpret_cast<const float4*>(
                    h_in + (size_t)(s >> 3) * HID + k0 + (s & 7) * 4));
            }
        };
        auto stchunk = [&]() {
            #pragma unroll
            for (int i = 0; i < 16; i++) {
                int s = lane + 32 * i;
                *reinterpret_cast<float4*>(&myA[(s >> 3) * AWS + (s & 7) * 4]) = pf[i];
            }
        };

        float acc[4][4][4];
        #pragma unroll
        for (int mt = 0; mt < 4; mt++)
            #pragma unroll
            for (int nt = 0; nt < 4; nt++)
                #pragma unroll
                for (int r = 0; r < 4; r++) acc[mt][nt][r] = 0.f;

        ldchunk(0);
        #pragma unroll
        for (int cc = 0; cc < 4; cc++) {
            stchunk();
            __syncwarp();
            if (cc < 3) ldchunk(cc + 1);

            #pragma unroll
            for (int k8i = 0; k8i < 4; k8i++) {
                const int kl = k8i * 8;                 // col in chunk buffer
                const int kg = kbase + cc * 32 + kl;    // global k for B
                unsigned a[4][4], b[4][2];
                #pragma unroll
                for (int mt = 0; mt < 4; mt++) {
                    int r0 = mt * 16 + (lane >> 2);
                    a[mt][0] = __float_as_uint(myA[r0 * AWS + kl + (lane & 3)]);
                    a[mt][1] = __float_as_uint(myA[(r0 + 8) * AWS + kl + (lane & 3)]);
                    a[mt][2] = __float_as_uint(myA[r0 * AWS + kl + (lane & 3) + 4]);
                    a[mt][3] = __float_as_uint(myA[(r0 + 8) * AWS + kl + (lane & 3) + 4]);
                }
                #pragma unroll
                for (int nt = 0; nt < 4; nt++) {
                    int rb = nt * 8 + (lane >> 2);
                    b[nt][0] = __float_as_uint(Bs[rb * BSTR + kg + (lane & 3)]);
                    b[nt][1] = __float_as_uint(Bs[rb * BSTR + kg + (lane & 3) + 4]);
                }
                #pragma unroll
                for (int mt = 0; mt < 4; mt++)
                    #pragma unroll
                    for (int nt = 0; nt < 4; nt++)
                        mma_tf32(acc[mt][nt], a[mt], b[nt]);
            }
            __syncwarp();
        }

        // ---- write partials into own buffer ----
        #pragma unroll
        for (int mt = 0; mt < 4; mt++)
            #pragma unroll
            for (int nt = 0; nt < 4; nt++)
                #pragma unroll
                for (int r = 0; r < 4; r++)
                    myA[((mt * 4 + nt) * 4 + r) * 32 + lane] = acc[mt][nt][r];
        __syncthreads();

        // ---- reduce across 8 warps + cell update (512 positions) ----
        #pragma unroll
        for (int pi = 0; pi < 2; pi++) {
            float g[4];
            #pragma unroll
            for (int nt = 0; nt < 4; nt++) {
                float s = 0.f;
                #pragma unroll
                for (int w = 0; w < 8; w++)
                    s += AwAll[w * AWF + base_pw[pi][nt]];
                g[nt] = s;
            }
            float gi = g[0] + gxr[pi][0];
            float gf = g[1] + gxr[pi][1];
            float gg = g[2] + gxr[pi][2];
            float go = g[3] + gxr[pi][3];
            float si = 1.f / (1.f + expf(-gi));
            float sf = 1.f / (1.f + expf(-gf));
            float so = 1.f / (1.f + expf(-go));
            float cn = sf * cr[pi] + si * tanhf(gg);
            float hn = so * tanhf(cn);
            int cidx = mm[pi] * HID + j0 + jjv[pi];
            g_c[cidx]   = cn;
            h_out[cidx] = tfr(hn);
        }
        __syncthreads();

        // ---- grid barrier (R8-proven form: monotonic counter + threadfence) ----
        if (tid == 0) {
            __threadfence();
            atomicAdd(&g_bar, 1u);
            unsigned target = (unsigned)(t + 1) * GRID;
            while (*(volatile unsigned*)&g_bar < target) { }
            __threadfence();
        }
        __syncthreads();
    }
}

// ============================================================================
// ar_step (unchanged): gates = g_b + h @ Wsum^T ; writes output
// ============================================================================
__global__ __launch_bounds__(256) void ar_step_kernel(int t, float* __restrict__ out_slot) {
    __shared__ float smem[64 * 36 + 32 * 36];
    float (*As)[36] = reinterpret_cast<float(*)[36]>(smem);
    float (*Bs)[36] = reinterpret_cast<float(*)[36]>(smem + 64 * 36);

    const int tid = threadIdx.x, wid = tid >> 5, lane = tid & 31;
    const int wn = wid & 3;
    const int wm = wid >> 2;
    const int j0 = blockIdx.x * 8;

    const float* __restrict__ h_in  = g_h[t & 1];
    float*       __restrict__ h_out = g_h[(t + 1) & 1];
    const float* __restrict__ W     = g_wsum;

    float c[2][4];
    #pragma unroll
    for (int mt = 0; mt < 2; mt++) {
        int jj = 2 * (lane & 3);
        int n  = wn * HID + j0 + jj;
        float b0 = g_b[n], b1 = g_b[n + 1];
        c[mt][0] = b0; c[mt][1] = b1;
        c[mt][2] = b0; c[mt][3] = b1;
    }

    float4 ra[2], rb;
    auto loadG = [&](int kc) {
        const int k0 = kc * 32;
        #pragma unroll
        for (int i = 0; i < 2; i++) {
            int l = tid + i * 256;
            int r = l >> 3, f = l & 7;
            ra[i] = *reinterpret_cast<const float4*>(h_in + (size_t)r * HID + k0 + f * 4);
        }
        {
            int r = tid >> 3, f = tid & 7;
            int gate = r >> 3, jj2 = r & 7;
            rb = *reinterpret_cast<const float4*>(
                W + (size_t)(gate * HID + j0 + jj2) * HID + k0 + f * 4);
        }
    };

    loadG(0);
    for (int kc = 0; kc < 32; kc++) {
        #pragma unroll
        for (int i = 0; i < 2; i++) {
            int l = tid + i * 256;
            int r = l >> 3, f = l & 7;
            float4 va = ra[i];
            va.x = tfr(va.x); va.y = tfr(va.y); va.z = tfr(va.z); va.w = tfr(va.w);
            *reinterpret_cast<float4*>(&As[r][f * 4]) = va;
        }
        {
            int r = tid >> 3, f = tid & 7;
            float4 vb = rb;
            vb.x = tfr(vb.x); vb.y = tfr(vb.y); vb.z = tfr(vb.z); vb.w = tfr(vb.w);
            *reinterpret_cast<float4*>(&Bs[r][f * 4]) = vb;
        }
        __syncthreads();
        if (kc + 1 < 32) loadG(kc + 1);

        #pragma unroll
        for (int kk = 0; kk < 4; kk++) {
            const int k8 = kk * 8;
            unsigned a[2][4], b[2];
            #pragma unroll
            for (int mt = 0; mt < 2; mt++) {
                int r0 = wm * 32 + mt * 16 + (lane >> 2);
                a[mt][0] = __float_as_uint(As[r0][k8 + (lane & 3)]);
                a[mt][1] = __float_as_uint(As[r0 + 8][k8 + (lane & 3)]);
                a[mt][2] = __float_as_uint(As[r0][k8 + (lane & 3) + 4]);
                a[mt][3] = __float_as_uint(As[r0 + 8][k8 + (lane & 3) + 4]);
            }
            {
                int rb2 = wn * 8 + (lane >> 2);
                b[0] = __float_as_uint(Bs[rb2][k8 + (lane & 3)]);
                b[1] = __float_as_uint(Bs[rb2][k8 + (lane & 3) + 4]);
            }
            #pragma unroll
            for (int mt = 0; mt < 2; mt++)
                mma_tf32(c[mt], a[mt], b);
        }
        __syncthreads();
    }

    float* sg = smem;
    #pragma unroll
    for (int mt = 0; mt < 2; mt++) {
        int row = wm * 32 + mt * 16 + (lane >> 2);
        int jj  = 2 * (lane & 3);
        sg[(wn * 64 + row) * 9 + jj]         = c[mt][0];
        sg[(wn * 64 + row) * 9 + jj + 1]     = c[mt][1];
        sg[(wn * 64 + row + 8) * 9 + jj]     = c[mt][2];
        sg[(wn * 64 + row + 8) * 9 + jj + 1] = c[mt][3];
    }
    __syncthreads();

    for (int q = tid; q < BATCH * 8; q += 256) {
        int m = q >> 3, jj = q & 7;
        float gi = sg[(0 * 64 + m) * 9 + jj];
        float gf = sg[(1 * 64 + m) * 9 + jj];
        float gg = sg[(2 * 64 + m) * 9 + jj];
        float go = sg[(3 * 64 + m) * 9 + jj];
        int cidx = m * HID + j0 + jj;
        float cold = g_c[cidx];
        float si = 1.f / (1.f + expf(-gi));
        float sf = 1.f / (1.f + expf(-gf));
        float so = 1.f / (1.f + expf(-go));
        float cn = sf * cold + si * tanhf(gg);
        float hn = so * tanhf(cn);
        g_c[cidx]      = cn;
        h_out[cidx]    = tfr(hn);
        out_slot[cidx] = hn;
    }
}

// ============================================================================
// launch
// ============================================================================
extern "C" void kernel_launch(void* const* d_in, const int* in_sizes, int n_in,
                              void* d_out, int out_size) {
    (void)in_sizes; (void)n_in; (void)out_size;
    const float* x    = (const float*)d_in[0];
    const float* hx0  = (const float*)d_in[1];
    const float* cx0  = (const float*)d_in[2];
    const float* W_ih = (const float*)d_in[3];
    const float* W_hh = (const float*)d_in[4];
    const float* b_ih = (const float*)d_in[5];
    const float* b_hh = (const float*)d_in[6];
    float* out = (float*)d_out;

    static bool attr_set = false;
    if (!attr_set) {
        cudaFuncSetAttribute(persist_kernel,
                             cudaFuncAttributeMaxDynamicSharedMemorySize, SM_TOTAL);
        cudaFuncSetAttribute(gemmA_kernel,
                             cudaFuncAttributeMaxDynamicSharedMemorySize, GA_SMEM);
        attr_set = true;
    }

    prep_kernel<<<(NG * HID + 255) / 256, 256>>>(W_ih, W_hh, b_ih, b_hh, hx0, cx0);

    dim3 gA(NG / 128, MTOT / 128);
    gemmA_kernel<<<gA, 256, GA_SMEM>>>(x, W_ih);

    persist_kernel<<<GRID, PTHR, SM_TOTAL>>>(W_hh);

    for (int t = S_LEN; t < S_LEN + 2; t++)
        ar_step_kernel<<<HID / 8, 256>>>(t, out + (size_t)(t - S_LEN) * BATCH * HID);
}